// round 3
// baseline (speedup 1.0000x reference)
#include <cuda_runtime.h>
#include <cuda_bf16.h>

// ---------------------------------------------------------------------------
// HGNN fused into ONE persistent kernel with software grid barriers.
// Phases: mask/detect -> passA -> buildS1 -> passB -> passC -> layer1 ->
//         layer2 -> head -> state reset (replay-safe).
// ---------------------------------------------------------------------------

#define NMAX     100000
#define MAX_S2   32
#define MAX_L2E  2048
#define MAX_S1   (MAX_L2E + MAX_S2)
#define H1TBL    4096
#define H1MASK   4095
#define RTBL     4096
#define RMASK    4095
#define RCAP     3500
#define MAX_L1E  32768
#define GRID     592
#define TPB      256

// All zero-initialized (CUDA zero-inits __device__ globals); the kernel
// restores them to zero at the end of every call.
__device__ float g_deg[NMAX];               // lazily zeroed at R-insert
__device__ int   g_h1pack[H1TBL];           // (slot<<17)|(node+1); 0 = empty
__device__ int   g_rtab[RTBL];              // node+1; 0 = empty
__device__ int   g_s2_node[MAX_S2];
__device__ float g_s2_val[MAX_S2];
__device__ int   g_s2_s1slot[MAX_S2];
__device__ int   g_l2_row[MAX_L2E];
__device__ int   g_l2_cslot[MAX_L2E];
__device__ int   g_l2_rslot[MAX_L2E];
__device__ float g_l2_w[MAX_L2E];
__device__ int   g_s1_node[MAX_S1];
__device__ int   g_l1_row[MAX_L1E];
__device__ int   g_l1_cslot[MAX_L1E];
__device__ float g_l1_w[MAX_L1E];
__device__ float g_h1[MAX_S1 * 256];
__device__ float g_z[256];
__device__ int   g_s2_count, g_l2e_count, g_l1e_count, g_s1_count, g_r_count, g_is32;
__device__ unsigned long long g_argmax_key;
__device__ unsigned          g_arrive;      // barrier arrival counter (returns to 0)
__device__ volatile unsigned g_phase;       // barrier phase (monotonic across replays)

__device__ __forceinline__ unsigned hsh(int v) {
    return ((unsigned)v * 2654435761u) >> 13;
}

// Grid-wide sense-reversing barrier. Every block calls it the same number of
// times; all GRID blocks are co-resident (residency checked in the analysis).
__device__ __forceinline__ void gsync(unsigned nb) {
    __syncthreads();
    if (threadIdx.x == 0) {
        unsigned ph = g_phase;
        __threadfence();
        if (atomicAdd(&g_arrive, 1u) == nb - 1u) {
            g_arrive = 0u;
            __threadfence();
            g_phase = ph + 1u;
        } else {
            while (g_phase == ph) __nanosleep(64);
        }
        __threadfence();
    }
    __syncthreads();
}

// R-set insert (global hash) + lazy zero of that node's degree.
__device__ void rtab_insert(int node) {
    if (g_r_count >= RCAP) return;
    unsigned idx = hsh(node) & RMASK;
    for (int p = 0; p < RTBL; p++) {
        int cur = atomicCAS(&g_rtab[idx], 0, node + 1);
        if (cur == 0) { g_deg[node] = 0.0f; atomicAdd(&g_r_count, 1); return; }
        if (cur == node + 1) return;
        idx = (idx + 1) & RMASK;
    }
}

__global__ __launch_bounds__(TPB) void hgnn_fused(
    const float* __restrict__ x,
    const long long* __restrict__ ei64,
    const float* __restrict__ ew,
    const float* __restrict__ mask,
    const long long* __restrict__ wt_idx,
    const long long* __restrict__ mut_idx,
    const float* __restrict__ W1, const float* __restrict__ b1,
    const float* __restrict__ W2, const float* __restrict__ b2,
    const float* __restrict__ aa_emb, const float* __restrict__ pos_emb,
    const float* __restrict__ Wh1, const float* __restrict__ bh1,
    const float* __restrict__ Wh2, const float* __restrict__ bh2,
    const float* __restrict__ Wh3, const float* __restrict__ bh3,
    float* __restrict__ out, int n, int E, int max_pos)
{
    __shared__ long long sbuf64[4096];               // 32 KB, reused per phase
    const int tid  = threadIdx.x;
    const int bid  = blockIdx.x;
    const unsigned nb = gridDim.x;
    const int gsz  = gridDim.x * blockDim.x;
    const int gtid = bid * blockDim.x + tid;
    const int* ei32 = (const int*)ei64;

    // ---------------- phase 0: dtype detect + mask scan -------------------
    {
        int lim = E < 4096 ? E : 4096;
        for (int i = gtid; i < lim; i += gsz) {
            long long v = ei64[i];
            if (v < 0 || v >= (long long)n) atomicExch(&g_is32, 1);
        }
        unsigned long long key = 0ull;
        for (int i = gtid; i < n; i += gsz) {
            float m = mask[i];
            if (m != 0.0f) {
                int slot = atomicAdd(&g_s2_count, 1);
                if (slot < MAX_S2) { g_s2_node[slot] = i; g_s2_val[slot] = m; }
            }
            unsigned int b  = __float_as_uint(m);
            unsigned int ub = (b & 0x80000000u) ? ~b : (b | 0x80000000u);
            unsigned long long k2 = (((unsigned long long)ub) << 32) |
                                    (unsigned long long)(0xFFFFFFFFu - (unsigned)i);
            if (k2 > key) key = k2;
        }
        unsigned long long* sk = (unsigned long long*)sbuf64;
        sk[tid] = key;
        __syncthreads();
        for (int o = 128; o > 0; o >>= 1) {
            if (tid < o) { unsigned long long a = sk[tid], b2 = sk[tid + o];
                           sk[tid] = (a > b2) ? a : b2; }
            __syncthreads();
        }
        if (tid == 0 && sk[0] != 0ull) atomicMax(&g_argmax_key, sk[0]);
    }
    gsync(nb);

    // ---------------- phase 1: passA (edges into S2) ----------------------
    {
        int ns2  = min(g_s2_count, MAX_S2);
        int is32 = g_is32;
        int* s2n = (int*)sbuf64;
        if (tid < ns2) s2n[tid] = g_s2_node[tid];
        __syncthreads();
        for (int e = gtid; e < E; e += gsz) {
            int c = is32 ? ei32[E + e] : (int)ei64[E + e];
            int ms = -1;
            for (int j = 0; j < ns2; j++) if (c == s2n[j]) ms = j;
            if (ms >= 0) {
                int r = is32 ? ei32[e] : (int)ei64[e];
                float w = ew[e];
                int slot = atomicAdd(&g_l2e_count, 1);
                if (slot < MAX_L2E) {
                    g_l2_row[slot] = r; g_l2_cslot[slot] = ms; g_l2_w[slot] = w;
                }
            }
        }
    }
    gsync(nb);

    // ---------------- phase 2: buildS1 (block 0 only) ---------------------
    if (bid == 0) {
        int nl2 = min(g_l2e_count, MAX_L2E);
        int ns2 = min(g_s2_count, MAX_S2);
        int items = nl2 + ns2;
        // 2a: dedup-insert node ids (node+1; slot assigned later)
        for (int i = tid; i < items; i += TPB) {
            int node = (i < nl2) ? g_l2_row[i] : g_s2_node[i - nl2];
            unsigned idx = hsh(node) & H1MASK;
            for (int p = 0; p < H1TBL; p++) {
                int cur = atomicCAS(&g_h1pack[idx], 0, node + 1);
                if (cur == 0 || (cur & 0x1FFFF) == node + 1) break;
                idx = (idx + 1) & H1MASK;
            }
        }
        __syncthreads();
        // 2b: assign dense slots by scanning the table; register in R set
        for (int i = tid; i < H1TBL; i += TPB) {
            int v = g_h1pack[i];
            if (v != 0) {
                int node = (v & 0x1FFFF) - 1;
                int s = atomicAdd(&g_s1_count, 1);
                g_h1pack[i] = (s << 17) | (v & 0x1FFFF);
                g_s1_node[s] = node;
                rtab_insert(node);
            }
        }
        __syncthreads();
        // 2c: resolve slots for L2 rows and S2 nodes
        for (int i = tid; i < items; i += TPB) {
            int node = (i < nl2) ? g_l2_row[i] : g_s2_node[i - nl2];
            unsigned idx = hsh(node) & H1MASK;
            int slot = -1;
            for (int p = 0; p < H1TBL; p++) {
                int v = g_h1pack[idx];
                if ((v & 0x1FFFF) == node + 1) { slot = v >> 17; break; }
                idx = (idx + 1) & H1MASK;
            }
            if (i < nl2) g_l2_rslot[i] = slot;
            else         g_s2_s1slot[i - nl2] = slot;
        }
    }
    gsync(nb);

    // ---------------- phase 3: passB (edges into S1) ----------------------
    {
        int* stab = (int*)sbuf64;                    // 16 KB packed table
        for (int i = tid; i < H1TBL; i += TPB) stab[i] = g_h1pack[i];
        __syncthreads();
        int is32 = g_is32;
        for (int e = gtid; e < E; e += gsz) {
            int c = is32 ? ei32[E + e] : (int)ei64[E + e];
            unsigned idx = hsh(c) & H1MASK;
            int slot = -1;
            for (int p = 0; p < H1TBL; p++) {
                int v = stab[idx];
                if (v == 0) break;
                if ((v & 0x1FFFF) == c + 1) { slot = v >> 17; break; }
                idx = (idx + 1) & H1MASK;
            }
            if (slot >= 0) {
                int r = is32 ? ei32[e] : (int)ei64[e];
                float w = ew[e];
                int pos = atomicAdd(&g_l1e_count, 1);
                if (pos < MAX_L1E) {
                    g_l1_row[pos] = r; g_l1_cslot[pos] = slot; g_l1_w[pos] = w;
                    rtab_insert(r);
                }
            }
        }
    }
    gsync(nb);

    // ---------------- phase 4: passC (degrees of R nodes) -----------------
    {
        int* rt = (int*)sbuf64;                      // 16 KB R table
        for (int i = tid; i < RTBL; i += TPB) rt[i] = g_rtab[i];
        __syncthreads();
        int is32 = g_is32;
        for (int e = gtid; e < E; e += gsz) {
            int c = is32 ? ei32[E + e] : (int)ei64[E + e];
            unsigned idx = hsh(c) & RMASK;
            bool hit = false;
            for (int p = 0; p < RTBL; p++) {
                int v = rt[idx];
                if (v == 0) break;
                if (v == c + 1) { hit = true; break; }
                idx = (idx + 1) & RMASK;
            }
            if (hit) atomicAdd(&g_deg[c], ew[e]);
        }
    }
    gsync(nb);

    // ---------------- phase 5: layer 1 (agg + GEMV, 128 -> 256) -----------
    {
        float* acc = (float*)sbuf64;                 // 128 floats
        int ns1 = g_s1_count;
        int nl1 = min(g_l1e_count, MAX_L1E);
        for (int s = bid; s < ns1; s += nb) {
            int node = g_s1_node[s];
            float degc = g_deg[node] + 1.0f;
            float dc = rsqrtf(degc);
            if (tid < 128) acc[tid] = x[(size_t)node * 128 + tid] / degc;
            __syncthreads();
            for (int e = 0; e < nl1; e++) {
                if (g_l1_cslot[e] == s) {
                    int r = g_l1_row[e];
                    float norm = g_l1_w[e] * rsqrtf(g_deg[r] + 1.0f) * dc;
                    if (tid < 128) acc[tid] += norm * x[(size_t)r * 128 + tid];
                }
            }
            __syncthreads();
            float aj = b1[tid];
#pragma unroll 8
            for (int k = 0; k < 128; k++) aj += acc[k] * W1[k * 256 + tid];
            g_h1[s * 256 + tid] = fmaxf(aj, 0.0f);
            __syncthreads();
        }
    }
    gsync(nb);

    // ---------------- phase 6: layer 2 + masked sum (block 0) -------------
    if (bid == 0) {
        float* agg = (float*)sbuf64;                 // 256 floats
        int ns2 = min(g_s2_count, MAX_S2);
        int nl2 = min(g_l2e_count, MAX_L2E);
        for (int s = 0; s < ns2; s++) {
            int cnode = g_s2_node[s];
            float degc = g_deg[cnode] + 1.0f;
            float dc = rsqrtf(degc);
            int cs1 = g_s2_s1slot[s];
            float a = g_h1[cs1 * 256 + tid] / degc;  // self loop
            for (int e = 0; e < nl2; e++) {
                if (g_l2_cslot[e] == s) {
                    int rnode = g_l2_row[e];
                    int rslot = g_l2_rslot[e];
                    float norm = g_l2_w[e] * rsqrtf(g_deg[rnode] + 1.0f) * dc;
                    a += norm * g_h1[rslot * 256 + tid];
                }
            }
            agg[tid] = a;
            __syncthreads();
            float aj = b2[tid];
#pragma unroll 8
            for (int k = 0; k < 256; k++) aj += agg[k] * W2[k * 256 + tid];
            g_z[tid] += g_s2_val[s] * fmaxf(aj, 0.0f);
            __syncthreads();
        }
    }
    gsync(nb);

    // ---------------- phase 7: MLP head (block 0) -------------------------
    if (bid == 0) {
        float* feat = (float*)sbuf64;                // 480
        float* f1   = feat + 480;                    // 512
        float* f2   = f1 + 512;                      // 128
        int is32 = g_is32;
        int wtI  = is32 ? ((const int*)wt_idx)[0]  : (int)wt_idx[0];
        int mutI = is32 ? ((const int*)mut_idx)[0] : (int)mut_idx[0];
        for (int j = tid; j < 480; j += TPB) {
            float v;
            if (j < 256)       v = g_z[j];
            else if (j < 320)  v = aa_emb[wtI  * 64 + (j - 256)];
            else if (j < 384)  v = aa_emb[mutI * 64 + (j - 320)];
            else if (j < 448)  v = aa_emb[mutI * 64 + (j - 384)] -
                                   aa_emb[wtI  * 64 + (j - 384)];
            else {
                unsigned int low = (unsigned int)(g_argmax_key & 0xFFFFFFFFull);
                int pos = (int)(0xFFFFFFFFu - low);
                if (pos < 0) pos = 0;
                if (pos > max_pos - 1) pos = max_pos - 1;
                v = pos_emb[pos * 32 + (j - 448)];
            }
            feat[j] = v;
        }
        __syncthreads();
        for (int j = tid; j < 512; j += TPB) {
            float acc = bh1[j];
#pragma unroll 8
            for (int k = 0; k < 480; k++) acc += feat[k] * Wh1[k * 512 + j];
            f1[j] = fmaxf(acc, 0.0f);
        }
        __syncthreads();
        if (tid < 128) {
            float acc = bh2[tid];
#pragma unroll 8
            for (int k = 0; k < 512; k++) acc += f1[k] * Wh2[k * 128 + tid];
            f2[tid] = fmaxf(acc, 0.0f) * Wh3[tid];
        }
        __syncthreads();
        if (tid < 64) f2[tid] += f2[tid + 64];
        __syncthreads();
        if (tid < 32) {
            float v = f2[tid] + f2[tid + 32];
            for (int o = 16; o > 0; o >>= 1) v += __shfl_down_sync(0xFFFFFFFFu, v, o);
            if (tid == 0) out[0] = v + bh3[0];
        }
    }
    gsync(nb);

    // ---------------- phase 8: reset state for next replay ----------------
    for (int i = gtid; i < H1TBL; i += gsz) g_h1pack[i] = 0;
    for (int i = gtid; i < RTBL;  i += gsz) g_rtab[i] = 0;
    for (int i = gtid; i < 256;   i += gsz) g_z[i] = 0.0f;
    if (gtid == 0) {
        g_s2_count = 0; g_l2e_count = 0; g_l1e_count = 0;
        g_s1_count = 0; g_r_count = 0; g_is32 = 0;
        g_argmax_key = 0ull;
    }
}

// ---------------------------------------------------------------------------
extern "C" void kernel_launch(void* const* d_in, const int* in_sizes, int n_in,
                              void* d_out, int out_size) {
    const float*     x       = (const float*)d_in[0];
    const long long* ei      = (const long long*)d_in[1];
    const float*     ew      = (const float*)d_in[2];
    const float*     mask    = (const float*)d_in[3];
    const long long* wt_idx  = (const long long*)d_in[4];
    const long long* mut_idx = (const long long*)d_in[5];
    const float*     W1      = (const float*)d_in[6];
    const float*     b1      = (const float*)d_in[7];
    const float*     W2      = (const float*)d_in[8];
    const float*     b2      = (const float*)d_in[9];
    const float*     aa_emb  = (const float*)d_in[10];
    const float*     pos_emb = (const float*)d_in[11];
    const float*     Wh1     = (const float*)d_in[12];
    const float*     bh1     = (const float*)d_in[13];
    const float*     Wh2     = (const float*)d_in[14];
    const float*     bh2     = (const float*)d_in[15];
    const float*     Wh3     = (const float*)d_in[16];
    const float*     bh3     = (const float*)d_in[17];
    float*           out     = (float*)d_out;

    int n       = in_sizes[3];
    int E       = in_sizes[2];
    int max_pos = in_sizes[11] / 32;

    hgnn_fused<<<GRID, TPB>>>(x, ei, ew, mask, wt_idx, mut_idx,
                              W1, b1, W2, b2, aa_emb, pos_emb,
                              Wh1, bh1, Wh2, bh2, Wh3, bh3,
                              out, n, E, max_pos);
}

// round 4
// speedup vs baseline: 1.4365x; 1.4365x over previous
#include <cuda_runtime.h>
#include <cuda_bf16.h>

// ---------------------------------------------------------------------------
// HGNN fused persistent kernel, v2: all GEMVs grid-parallel, 296 blocks,
// vectorized edge streams, 9 software grid barriers.
// ---------------------------------------------------------------------------

#define NMAX     100000
#define MAX_S2   32
#define MAX_L2E  2048
#define MAX_S1   (MAX_L2E + MAX_S2)
#define H1TBL    4096
#define H1MASK   4095
#define RTBL     4096
#define RMASK    4095
#define RCAP     3500
#define MAX_L1E  32768
#define GRID     296
#define TPB      256

__device__ float g_deg[NMAX];               // lazily zeroed at rtab_insert
__device__ int   g_h1pack[H1TBL];           // (slot<<17)|(node+1); 0 = empty
__device__ int   g_rtab[RTBL];              // node+1; 0 = empty
__device__ int   g_s2_node[MAX_S2];
__device__ float g_s2_val[MAX_S2];
__device__ int   g_s2_s1slot[MAX_S2];
__device__ int   g_l2_row[MAX_L2E];
__device__ int   g_l2_cslot[MAX_L2E];
__device__ int   g_l2_rslot[MAX_L2E];
__device__ float g_l2_w[MAX_L2E];
__device__ int   g_s1_node[MAX_S1];
__device__ int   g_l1_row[MAX_L1E];
__device__ int   g_l1_cslot[MAX_L1E];
__device__ float g_l1_w[MAX_L1E];
__device__ float g_h1[MAX_S1 * 256];
__device__ float g_z[256];
__device__ float g_feat_hi[224];            // feat[256..480): aa & pos parts
__device__ float g_f1[512];
__device__ int   g_s2_count, g_l2e_count, g_l1e_count, g_s1_count, g_r_count, g_is32;
__device__ unsigned long long g_argmax_key;
__device__ unsigned          g_arrive;
__device__ volatile unsigned g_phase;       // monotonic across replays

__device__ __forceinline__ unsigned hsh(int v) {
    return ((unsigned)v * 2654435761u) >> 13;
}

__device__ __forceinline__ void gsync(unsigned nb) {
    __syncthreads();
    if (threadIdx.x == 0) {
        unsigned ph = g_phase;
        __threadfence();
        if (atomicAdd(&g_arrive, 1u) == nb - 1u) {
            g_arrive = 0u;
            __threadfence();
            g_phase = ph + 1u;
        } else {
            while (g_phase == ph) __nanosleep(32);
        }
        __threadfence();
    }
    __syncthreads();
}

__device__ void rtab_insert(int node) {
    if (g_r_count >= RCAP) return;
    unsigned idx = hsh(node) & RMASK;
    for (int p = 0; p < RTBL; p++) {
        int cur = atomicCAS(&g_rtab[idx], 0, node + 1);
        if (cur == 0) { g_deg[node] = 0.0f; atomicAdd(&g_r_count, 1); return; }
        if (cur == node + 1) return;
        idx = (idx + 1) & RMASK;
    }
}

// --- per-edge probe bodies -------------------------------------------------
__device__ __forceinline__ void probeA(int c, int e, int ns2, const int* s2n,
                                       const long long* ei64, const int* ei32,
                                       const float* ew, int E, int is32) {
    int ms = -1;
    for (int j = 0; j < ns2; j++) if (c == s2n[j]) ms = j;
    if (ms >= 0) {
        int r = is32 ? ei32[e] : (int)ei64[e];
        float w = ew[e];
        int slot = atomicAdd(&g_l2e_count, 1);
        if (slot < MAX_L2E) {
            g_l2_row[slot] = r; g_l2_cslot[slot] = ms; g_l2_w[slot] = w;
        }
    }
}

__device__ __forceinline__ void probeB(int c, int e, const int* stab,
                                       const long long* ei64, const int* ei32,
                                       const float* ew, int E, int is32) {
    unsigned idx = hsh(c) & H1MASK;
    int slot = -1;
    for (int p = 0; p < H1TBL; p++) {
        int v = stab[idx];
        if (v == 0) break;
        if ((v & 0x1FFFF) == c + 1) { slot = v >> 17; break; }
        idx = (idx + 1) & H1MASK;
    }
    if (slot >= 0) {
        int r = is32 ? ei32[e] : (int)ei64[e];
        float w = ew[e];
        int pos = atomicAdd(&g_l1e_count, 1);
        if (pos < MAX_L1E) {
            g_l1_row[pos] = r; g_l1_cslot[pos] = slot; g_l1_w[pos] = w;
            rtab_insert(r);
        }
    }
}

__device__ __forceinline__ void probeC(int c, int e, const int* rt,
                                       const float* ew) {
    unsigned idx = hsh(c) & RMASK;
    for (int p = 0; p < RTBL; p++) {
        int v = rt[idx];
        if (v == 0) return;
        if (v == c + 1) { atomicAdd(&g_deg[c], ew[e]); return; }
        idx = (idx + 1) & RMASK;
    }
}

__global__ __launch_bounds__(TPB) void hgnn_fused(
    const float* __restrict__ x,
    const long long* __restrict__ ei64,
    const float* __restrict__ ew,
    const float* __restrict__ mask,
    const long long* __restrict__ wt_idx,
    const long long* __restrict__ mut_idx,
    const float* __restrict__ W1, const float* __restrict__ b1,
    const float* __restrict__ W2, const float* __restrict__ b2,
    const float* __restrict__ aa_emb, const float* __restrict__ pos_emb,
    const float* __restrict__ Wh1, const float* __restrict__ bh1,
    const float* __restrict__ Wh2, const float* __restrict__ bh2,
    const float* __restrict__ Wh3, const float* __restrict__ bh3,
    float* __restrict__ out, int n, int E, int max_pos)
{
    __shared__ long long sbuf64[4096];               // 32 KB scratch
    const int tid  = threadIdx.x;
    const int bid  = blockIdx.x;
    const unsigned nb = gridDim.x;
    const int gsz  = gridDim.x * blockDim.x;
    const int gtid = bid * blockDim.x + tid;
    const int* ei32 = (const int*)ei64;

    // ============ phase 0: dtype detect + mask scan + out bias ============
    {
        int lim = E < 4096 ? E : 4096;
        for (int i = gtid; i < lim; i += gsz) {
            long long v = ei64[i];
            if (v < 0 || v >= (long long)n) atomicExch(&g_is32, 1);
        }
        if (gtid == 0) out[0] = bh3[0];
        unsigned long long key = 0ull;
        for (int i = gtid; i < n; i += gsz) {
            float m = mask[i];
            if (m != 0.0f) {
                int slot = atomicAdd(&g_s2_count, 1);
                if (slot < MAX_S2) { g_s2_node[slot] = i; g_s2_val[slot] = m; }
            }
            unsigned int b  = __float_as_uint(m);
            unsigned int ub = (b & 0x80000000u) ? ~b : (b | 0x80000000u);
            unsigned long long k2 = (((unsigned long long)ub) << 32) |
                                    (unsigned long long)(0xFFFFFFFFu - (unsigned)i);
            if (k2 > key) key = k2;
        }
        unsigned long long* sk = (unsigned long long*)sbuf64;
        sk[tid] = key;
        __syncthreads();
        for (int o = 128; o > 0; o >>= 1) {
            if (tid < o) { unsigned long long a = sk[tid], b2 = sk[tid + o];
                           sk[tid] = (a > b2) ? a : b2; }
            __syncthreads();
        }
        if (tid == 0 && sk[0] != 0ull) atomicMax(&g_argmax_key, sk[0]);
    }
    gsync(nb);

    // ============ phase 1: passA (edges into S2), vectorized ==============
    {
        int ns2  = min(g_s2_count, MAX_S2);
        int is32 = g_is32;
        int* s2n = (int*)sbuf64;
        if (tid < ns2) s2n[tid] = g_s2_node[tid];
        __syncthreads();
        if (is32) {
            const int4* col4 = (const int4*)(ei32 + E);
            int nvec = E >> 2;
            for (int v = gtid; v < nvec; v += gsz) {
                int4 c4 = col4[v];
                int e = v * 4;
                probeA(c4.x, e,     ns2, s2n, ei64, ei32, ew, E, 1);
                probeA(c4.y, e + 1, ns2, s2n, ei64, ei32, ew, E, 1);
                probeA(c4.z, e + 2, ns2, s2n, ei64, ei32, ew, E, 1);
                probeA(c4.w, e + 3, ns2, s2n, ei64, ei32, ew, E, 1);
            }
            for (int e = nvec * 4 + gtid; e < E; e += gsz)
                probeA(ei32[E + e], e, ns2, s2n, ei64, ei32, ew, E, 1);
        } else {
            const longlong2* col2 = (const longlong2*)(ei64 + E);
            int nvec = E >> 1;
            for (int v = gtid; v < nvec; v += gsz) {
                longlong2 c2 = col2[v];
                int e = v * 2;
                probeA((int)c2.x, e,     ns2, s2n, ei64, ei32, ew, E, 0);
                probeA((int)c2.y, e + 1, ns2, s2n, ei64, ei32, ew, E, 0);
            }
            for (int e = nvec * 2 + gtid; e < E; e += gsz)
                probeA((int)ei64[E + e], e, ns2, s2n, ei64, ei32, ew, E, 0);
        }
    }
    gsync(nb);

    // ============ phase 2: buildS1 (block 0) + feat_hi (block 1) ==========
    if (bid == 0) {
        int nl2 = min(g_l2e_count, MAX_L2E);
        int ns2 = min(g_s2_count, MAX_S2);
        int items = nl2 + ns2;
        for (int i = tid; i < items; i += TPB) {          // 2a dedup insert
            int node = (i < nl2) ? g_l2_row[i] : g_s2_node[i - nl2];
            unsigned idx = hsh(node) & H1MASK;
            for (int p = 0; p < H1TBL; p++) {
                int cur = atomicCAS(&g_h1pack[idx], 0, node + 1);
                if (cur == 0 || (cur & 0x1FFFF) == node + 1) break;
                idx = (idx + 1) & H1MASK;
            }
        }
        __syncthreads();
        for (int i = tid; i < H1TBL; i += TPB) {          // 2b assign slots
            int v = g_h1pack[i];
            if (v != 0) {
                int node = (v & 0x1FFFF) - 1;
                int s = atomicAdd(&g_s1_count, 1);
                g_h1pack[i] = (s << 17) | (v & 0x1FFFF);
                g_s1_node[s] = node;
                rtab_insert(node);
            }
        }
        __syncthreads();
        for (int i = tid; i < items; i += TPB) {          // 2c resolve slots
            int node = (i < nl2) ? g_l2_row[i] : g_s2_node[i - nl2];
            unsigned idx = hsh(node) & H1MASK;
            int slot = -1;
            for (int p = 0; p < H1TBL; p++) {
                int v = g_h1pack[idx];
                if ((v & 0x1FFFF) == node + 1) { slot = v >> 17; break; }
                idx = (idx + 1) & H1MASK;
            }
            if (i < nl2) g_l2_rslot[i] = slot;
            else         g_s2_s1slot[i - nl2] = slot;
        }
    } else if (bid == 1) {
        int is32 = g_is32;
        int wtI  = is32 ? ((const int*)wt_idx)[0]  : (int)wt_idx[0];
        int mutI = is32 ? ((const int*)mut_idx)[0] : (int)mut_idx[0];
        if (tid < 224) {
            float v;
            if (tid < 64)       v = aa_emb[wtI  * 64 + tid];
            else if (tid < 128) v = aa_emb[mutI * 64 + (tid - 64)];
            else if (tid < 192) v = aa_emb[mutI * 64 + (tid - 128)] -
                                    aa_emb[wtI  * 64 + (tid - 128)];
            else {
                unsigned int low = (unsigned int)(g_argmax_key & 0xFFFFFFFFull);
                int pos = (int)(0xFFFFFFFFu - low);
                if (pos < 0) pos = 0;
                if (pos > max_pos - 1) pos = max_pos - 1;
                v = pos_emb[pos * 32 + (tid - 192)];
            }
            g_feat_hi[tid] = v;
        }
    }
    gsync(nb);

    // ============ phase 3: passB (edges into S1), vectorized ==============
    {
        int* stab = (int*)sbuf64;                         // 16 KB table copy
        for (int i = tid; i < H1TBL; i += TPB) stab[i] = g_h1pack[i];
        __syncthreads();
        int is32 = g_is32;
        if (is32) {
            const int4* col4 = (const int4*)(ei32 + E);
            int nvec = E >> 2;
            for (int v = gtid; v < nvec; v += gsz) {
                int4 c4 = col4[v];
                int e = v * 4;
                probeB(c4.x, e,     stab, ei64, ei32, ew, E, 1);
                probeB(c4.y, e + 1, stab, ei64, ei32, ew, E, 1);
                probeB(c4.z, e + 2, stab, ei64, ei32, ew, E, 1);
                probeB(c4.w, e + 3, stab, ei64, ei32, ew, E, 1);
            }
            for (int e = nvec * 4 + gtid; e < E; e += gsz)
                probeB(ei32[E + e], e, stab, ei64, ei32, ew, E, 1);
        } else {
            const longlong2* col2 = (const longlong2*)(ei64 + E);
            int nvec = E >> 1;
            for (int v = gtid; v < nvec; v += gsz) {
                longlong2 c2 = col2[v];
                int e = v * 2;
                probeB((int)c2.x, e,     stab, ei64, ei32, ew, E, 0);
                probeB((int)c2.y, e + 1, stab, ei64, ei32, ew, E, 0);
            }
            for (int e = nvec * 2 + gtid; e < E; e += gsz)
                probeB((int)ei64[E + e], e, stab, ei64, ei32, ew, E, 0);
        }
    }
    gsync(nb);

    // ============ phase 4: passC (degrees of R nodes), vectorized =========
    {
        int* rt = (int*)sbuf64;
        for (int i = tid; i < RTBL; i += TPB) rt[i] = g_rtab[i];
        __syncthreads();
        int is32 = g_is32;
        if (is32) {
            const int4* col4 = (const int4*)(ei32 + E);
            int nvec = E >> 2;
            for (int v = gtid; v < nvec; v += gsz) {
                int4 c4 = col4[v];
                int e = v * 4;
                probeC(c4.x, e,     rt, ew);
                probeC(c4.y, e + 1, rt, ew);
                probeC(c4.z, e + 2, rt, ew);
                probeC(c4.w, e + 3, rt, ew);
            }
            for (int e = nvec * 4 + gtid; e < E; e += gsz)
                probeC(ei32[E + e], e, rt, ew);
        } else {
            const longlong2* col2 = (const longlong2*)(ei64 + E);
            int nvec = E >> 1;
            for (int v = gtid; v < nvec; v += gsz) {
                longlong2 c2 = col2[v];
                int e = v * 2;
                probeC((int)c2.x, e,     rt, ew);
                probeC((int)c2.y, e + 1, rt, ew);
            }
            for (int e = nvec * 2 + gtid; e < E; e += gsz)
                probeC((int)ei64[E + e], e, rt, ew);
        }
    }
    gsync(nb);

    // ============ phase 5: layer 1 (agg + GEMV 128->256 per S1 slot) ======
    {
        float* acc = (float*)sbuf64;                      // 128 floats
        int ns1 = g_s1_count;
        int nl1 = min(g_l1e_count, MAX_L1E);
        for (int s = bid; s < ns1; s += nb) {
            int node = g_s1_node[s];
            float degc = g_deg[node] + 1.0f;
            float dc = rsqrtf(degc);
            if (tid < 128) acc[tid] = x[(size_t)node * 128 + tid] / degc;
            __syncthreads();
#pragma unroll 4
            for (int e = 0; e < nl1; e++) {
                if (g_l1_cslot[e] == s) {
                    int r = g_l1_row[e];
                    float norm = g_l1_w[e] * rsqrtf(g_deg[r] + 1.0f) * dc;
                    if (tid < 128) acc[tid] += norm * x[(size_t)r * 128 + tid];
                }
            }
            __syncthreads();
            float aj = b1[tid];
#pragma unroll 8
            for (int k = 0; k < 128; k++) aj += acc[k] * W1[k * 256 + tid];
            g_h1[s * 256 + tid] = fmaxf(aj, 0.0f);
            __syncthreads();
        }
    }
    gsync(nb);

    // ============ phase 6: layer 2 GEMV + masked sum (ns2*8 blocks) =======
    {
        int ns2 = min(g_s2_count, MAX_S2);
        int nl2 = min(g_l2e_count, MAX_L2E);
        int nblk = ns2 * 8;
        if (bid < nblk) {
            int s  = bid >> 3;
            int j0 = (bid & 7) << 5;
            float* sagg  = (float*)sbuf64;                // 256
            float* spart = sagg + 256;                    // 256
            // recompute agg[256] (tiny, redundant across the 8 sibling blocks)
            {
                int cnode = g_s2_node[s];
                float degc = g_deg[cnode] + 1.0f;
                float dc = rsqrtf(degc);
                int cs1 = g_s2_s1slot[s];
                float a = g_h1[cs1 * 256 + tid] / degc;
                for (int e = 0; e < nl2; e++) {
                    if (g_l2_cslot[e] == s) {
                        int rnode = g_l2_row[e];
                        int rslot = g_l2_rslot[e];
                        float norm = g_l2_w[e] * rsqrtf(g_deg[rnode] + 1.0f) * dc;
                        a += norm * g_h1[rslot * 256 + tid];
                    }
                }
                sagg[tid] = a;
            }
            __syncthreads();
            int j  = j0 + (tid & 31);
            int kc = tid >> 5;
            float acc = 0.0f;
#pragma unroll 8
            for (int k = kc * 32; k < kc * 32 + 32; k++)
                acc += sagg[k] * W2[k * 256 + j];
            spart[tid] = acc;
            __syncthreads();
            if (tid < 32) {
                float sum = b2[j0 + tid];
#pragma unroll
                for (int c = 0; c < 8; c++) sum += spart[c * 32 + tid];
                atomicAdd(&g_z[j0 + tid], g_s2_val[s] * fmaxf(sum, 0.0f));
            }
        }
    }
    gsync(nb);

    // ============ phase 7: head GEMV1 480->512 (16 blocks) ================
    if (bid < 16) {
        float* sfeat = (float*)sbuf64;                    // 480
        float* spart = sfeat + 480;                       // 256
        if (tid < 256) sfeat[tid] = g_z[tid];
        if (tid < 224) sfeat[256 + tid] = g_feat_hi[tid];
        __syncthreads();
        int j0 = bid * 32;
        int j  = j0 + (tid & 31);
        int kc = tid >> 5;
        float acc = 0.0f;
#pragma unroll 10
        for (int k = kc * 60; k < kc * 60 + 60; k++)
            acc += sfeat[k] * Wh1[k * 512 + j];
        spart[tid] = acc;
        __syncthreads();
        if (tid < 32) {
            float sum = bh1[j0 + tid];
#pragma unroll
            for (int c = 0; c < 8; c++) sum += spart[c * 32 + tid];
            g_f1[j0 + tid] = fmaxf(sum, 0.0f);
        }
    }
    gsync(nb);

    // ============ phase 8: head GEMV2 512->128, dot with Wh3 (4 blocks) ===
    if (bid < 4) {
        float* sf1   = (float*)sbuf64;                    // 512
        float* spart = sf1 + 512;                         // 256
        sf1[tid]       = g_f1[tid];
        sf1[tid + 256] = g_f1[tid + 256];
        __syncthreads();
        int j0 = bid * 32;
        int j  = j0 + (tid & 31);
        int kc = tid >> 5;
        float acc = 0.0f;
#pragma unroll 8
        for (int k = kc * 64; k < kc * 64 + 64; k++)
            acc += sf1[k] * Wh2[k * 128 + j];
        spart[tid] = acc;
        __syncthreads();
        if (tid < 32) {
            float sum = bh2[j0 + tid];
#pragma unroll
            for (int c = 0; c < 8; c++) sum += spart[c * 32 + tid];
            float v = fmaxf(sum, 0.0f) * Wh3[j0 + tid];
            for (int o = 16; o > 0; o >>= 1) v += __shfl_down_sync(0xFFFFFFFFu, v, o);
            if (tid == 0) atomicAdd(out, v);
        }
    }
    gsync(nb);

    // ============ phase 9: reset state for next replay ====================
    for (int i = gtid; i < H1TBL; i += gsz) g_h1pack[i] = 0;
    for (int i = gtid; i < RTBL;  i += gsz) g_rtab[i] = 0;
    for (int i = gtid; i < 256;   i += gsz) g_z[i] = 0.0f;
    if (gtid == 0) {
        g_s2_count = 0; g_l2e_count = 0; g_l1e_count = 0;
        g_s1_count = 0; g_r_count = 0; g_is32 = 0;
        g_argmax_key = 0ull;
    }
}

// ---------------------------------------------------------------------------
extern "C" void kernel_launch(void* const* d_in, const int* in_sizes, int n_in,
                              void* d_out, int out_size) {
    const float*     x       = (const float*)d_in[0];
    const long long* ei      = (const long long*)d_in[1];
    const float*     ew      = (const float*)d_in[2];
    const float*     mask    = (const float*)d_in[3];
    const long long* wt_idx  = (const long long*)d_in[4];
    const long long* mut_idx = (const long long*)d_in[5];
    const float*     W1      = (const float*)d_in[6];
    const float*     b1      = (const float*)d_in[7];
    const float*     W2      = (const float*)d_in[8];
    const float*     b2      = (const float*)d_in[9];
    const float*     aa_emb  = (const float*)d_in[10];
    const float*     pos_emb = (const float*)d_in[11];
    const float*     Wh1     = (const float*)d_in[12];
    const float*     bh1     = (const float*)d_in[13];
    const float*     Wh2     = (const float*)d_in[14];
    const float*     bh2     = (const float*)d_in[15];
    const float*     Wh3     = (const float*)d_in[16];
    const float*     bh3     = (const float*)d_in[17];
    float*           out     = (float*)d_out;

    int n       = in_sizes[3];
    int E       = in_sizes[2];
    int max_pos = in_sizes[11] / 32;

    hgnn_fused<<<GRID, TPB>>>(x, ei, ew, mask, wt_idx, mut_idx,
                              W1, b1, W2, b2, aa_emb, pos_emb,
                              Wh1, bh1, Wh2, bh2, Wh3, bh3,
                              out, n, E, max_pos);
}

// round 5
// speedup vs baseline: 1.6284x; 1.1336x over previous
#include <cuda_runtime.h>
#include <cuda_bf16.h>

// ---------------------------------------------------------------------------
// HGNN fused persistent kernel v3: 4 full barriers + 3 mini barriers,
// no nanosleep, 148x512, inline S1 hash build, exit-early tail.
// ---------------------------------------------------------------------------

#define NMAX     100000
#define MAX_S2   32
#define MAX_L2E  2048
#define MAX_S1   (MAX_L2E + MAX_S2 + 32)
#define H1TBL    4096
#define H1MASK   4095
#define RTBL     4096
#define RMASK    4095
#define RCAP     3500
#define MAX_L1E  32768
#define GRID     148
#define TPB      512

__device__ float g_deg[NMAX];                 // lazily zeroed at rtab_insert
__device__ int   g_h1pack[H1TBL];             // (slot<<17)|(node+1); 0 empty
__device__ int   g_rtab[RTBL];                // node+1; 0 empty
__device__ int   g_s2_node[MAX_S2];
__device__ float g_s2_val[MAX_S2];
__device__ int   g_s2_s1slot[MAX_S2];
__device__ int   g_l2_row[MAX_L2E];
__device__ int   g_l2_cslot[MAX_L2E];
__device__ int   g_l2_rslot[MAX_L2E];
__device__ float g_l2_w[MAX_L2E];
__device__ int   g_s1_node[MAX_S1];           // -1 = wasted slot
__device__ int   g_l1_row[MAX_L1E];
__device__ int   g_l1_cslot[MAX_L1E];
__device__ float g_l1_w[MAX_L1E];
__device__ float g_h1[MAX_S1 * 256];
__device__ float g_z[256];
__device__ float g_f1[512];
__device__ int   g_s2_count, g_l2e_count, g_l1e_count, g_s1_count, g_r_count, g_is32;
__device__ unsigned long long g_argmax_key;
__device__ unsigned          g_arrive;
__device__ volatile unsigned g_phase;         // monotonic across replays
__device__ int               g_marr[3];
__device__ volatile unsigned g_mph[3];        // monotonic mini phases

__device__ __forceinline__ unsigned hsh(int v) {
    return ((unsigned)v * 2654435761u) >> 13;
}

__device__ void rtab_insert(int node) {
    if (g_r_count >= RCAP) return;
    unsigned idx = hsh(node) & RMASK;
    for (int p = 0; p < RTBL; p++) {
        int cur = atomicCAS(&g_rtab[idx], 0, node + 1);
        if (cur == 0) { g_deg[node] = 0.0f; atomicAdd(&g_r_count, 1); return; }
        if (cur == node + 1) return;
        idx = (idx + 1) & RMASK;
    }
}

// Insert node into S1 hash; returns its dense slot (existing or new).
// Slot is packed into the table word by a single CAS, so any reader of a
// nonzero entry sees a complete (slot,node) pair. Duplicate-insert races
// burn a slot, marked invalid via g_s1_node = -1.
__device__ int h1_insert(int node) {
    unsigned idx = hsh(node) & H1MASK;
    int myslot = -1;
    for (int p = 0; p < H1TBL; p++) {
        int v = g_h1pack[idx];
        if (v != 0) {
            if ((v & 0x1FFFF) == node + 1) {
                if (myslot >= 0) g_s1_node[myslot] = -1;
                return v >> 17;
            }
        } else {
            if (myslot < 0) {
                myslot = atomicAdd(&g_s1_count, 1);
                if (myslot >= MAX_S1) return -1;          // overflow guard
            }
            int cur = atomicCAS(&g_h1pack[idx], 0, (myslot << 17) | (node + 1));
            if (cur == 0) {
                g_s1_node[myslot] = node;
                rtab_insert(node);
                return myslot;
            }
            if ((cur & 0x1FFFF) == node + 1) {
                g_s1_node[myslot] = -1;
                return cur >> 17;
            }
        }
        idx = (idx + 1) & H1MASK;
    }
    return -1;
}

__global__ __launch_bounds__(TPB) void hgnn_fused(
    const float* __restrict__ x,
    const long long* __restrict__ ei64,
    const float* __restrict__ ew,
    const float* __restrict__ mask,
    const long long* __restrict__ wt_idx,
    const long long* __restrict__ mut_idx,
    const float* __restrict__ W1, const float* __restrict__ b1,
    const float* __restrict__ W2, const float* __restrict__ b2,
    const float* __restrict__ aa_emb, const float* __restrict__ pos_emb,
    const float* __restrict__ Wh1, const float* __restrict__ bh1,
    const float* __restrict__ Wh2, const float* __restrict__ bh2,
    const float* __restrict__ Wh3, const float* __restrict__ bh3,
    float* __restrict__ out, int n, int E, int max_pos)
{
    __shared__ long long sbuf64[4096];                // 32 KB scratch
    const int tid  = threadIdx.x;
    const int bid  = blockIdx.x;
    const int gsz  = GRID * TPB;
    const int gtid = bid * TPB + tid;
    const int* ei32 = (const int*)ei64;

    // capture monotonic phases (stable at kernel entry)
    unsigned ph   = g_phase;
    unsigned mp0  = g_mph[0], mp1 = g_mph[1], mp2 = g_mph[2];

    // local barrier helpers (macros to keep register state simple)
#define GSYNC() do {                                                         \
        __syncthreads();                                                     \
        if (tid == 0) {                                                      \
            __threadfence();                                                 \
            if (atomicAdd(&g_arrive, 1u) == GRID - 1u) {                     \
                g_arrive = 0u; __threadfence(); g_phase = ph + 1u;           \
            } else { while (g_phase == ph) { } }                             \
            __threadfence();                                                 \
        }                                                                    \
        __syncthreads(); ph++;                                               \
    } while (0)

#define MARRIVE(id, total, mpv) do {                                         \
        __syncthreads();                                                     \
        if (tid == 0) {                                                      \
            __threadfence();                                                 \
            if (atomicAdd(&g_marr[id], 1) == (total) - 1) {                  \
                g_marr[id] = 0; __threadfence(); g_mph[id] = (mpv) + 1u;     \
            }                                                                \
        }                                                                    \
    } while (0)

#define MWAIT(id, mpv) do {                                                  \
        if (tid == 0) { while (g_mph[id] == (mpv)) { } __threadfence(); }    \
        __syncthreads();                                                     \
    } while (0)

    // ============ phase 0: dtype detect + mask scan =======================
    {
        int lim = E < 4096 ? E : 4096;
        for (int i = gtid; i < lim; i += gsz) {
            long long v = ei64[i];
            if (v < 0 || v >= (long long)n) atomicExch(&g_is32, 1);
        }
        unsigned long long key = 0ull;
        for (int i = gtid; i < n; i += gsz) {
            float m = mask[i];
            if (m != 0.0f) {
                int slot = atomicAdd(&g_s2_count, 1);
                if (slot < MAX_S2) {
                    g_s2_node[slot] = i; g_s2_val[slot] = m;
                    g_s2_s1slot[slot] = h1_insert(i);
                }
            }
            unsigned int b  = __float_as_uint(m);
            unsigned int ub = (b & 0x80000000u) ? ~b : (b | 0x80000000u);
            unsigned long long k2 = (((unsigned long long)ub) << 32) |
                                    (unsigned long long)(0xFFFFFFFFu - (unsigned)i);
            if (k2 > key) key = k2;
        }
        unsigned long long* sk = (unsigned long long*)sbuf64;
        sk[tid] = key;
        __syncthreads();
        for (int o = 256; o > 0; o >>= 1) {
            if (tid < o) { unsigned long long a = sk[tid], b2 = sk[tid + o];
                           sk[tid] = (a > b2) ? a : b2; }
            __syncthreads();
        }
        if (tid == 0 && sk[0] != 0ull) atomicMax(&g_argmax_key, sk[0]);
    }
    GSYNC();

    // ============ phase 1: passA (edges into S2) + inline S1 build ========
    {
        int ns2  = min(g_s2_count, MAX_S2);
        int is32 = g_is32;
        int* s2n = (int*)sbuf64;
        if (tid < ns2) s2n[tid] = g_s2_node[tid];
        __syncthreads();
#define DO_A(cc, ee) do {                                                    \
            int _c = (cc); int _ms = -1;                                     \
            for (int _j = 0; _j < ns2; _j++) if (_c == s2n[_j]) _ms = _j;    \
            if (_ms >= 0) {                                                  \
                int _e = (ee);                                               \
                int _r = is32 ? ei32[_e] : (int)ei64[_e];                    \
                int _sl = atomicAdd(&g_l2e_count, 1);                        \
                if (_sl < MAX_L2E) {                                         \
                    g_l2_row[_sl] = _r; g_l2_cslot[_sl] = _ms;               \
                    g_l2_w[_sl] = ew[_e];                                    \
                    g_l2_rslot[_sl] = h1_insert(_r);                         \
                }                                                            \
            }                                                                \
        } while (0)
        if (is32) {
            const int4* col4 = (const int4*)(ei32 + E);
            int nvec = E >> 2;
            for (int v = gtid; v < nvec; v += gsz) {
                int4 c4 = col4[v]; int e = v * 4;
                DO_A(c4.x, e); DO_A(c4.y, e + 1); DO_A(c4.z, e + 2); DO_A(c4.w, e + 3);
            }
            for (int e = (nvec << 2) + gtid; e < E; e += gsz) DO_A(ei32[E + e], e);
        } else {
            const longlong2* col2 = (const longlong2*)(ei64 + E);
            int nvec = E >> 1;
            for (int v = gtid; v < nvec; v += gsz) {
                longlong2 c2 = col2[v]; int e = v * 2;
                DO_A((int)c2.x, e); DO_A((int)c2.y, e + 1);
            }
            for (int e = (nvec << 1) + gtid; e < E; e += gsz) DO_A((int)ei64[E + e], e);
        }
#undef DO_A
    }
    GSYNC();

    // ============ phase 2: passB (edges into S1) ==========================
    {
        int* stab = (int*)sbuf64;                         // 16 KB
        for (int i = tid; i < H1TBL; i += TPB) stab[i] = g_h1pack[i];
        __syncthreads();
        int is32 = g_is32;
#define DO_B(cc, ee) do {                                                    \
            int _c = (cc);                                                   \
            unsigned _ix = hsh(_c) & H1MASK; int _sl = -1;                   \
            for (int _p = 0; _p < H1TBL; _p++) {                             \
                int _v = stab[_ix];                                          \
                if (_v == 0) break;                                          \
                if ((_v & 0x1FFFF) == _c + 1) { _sl = _v >> 17; break; }     \
                _ix = (_ix + 1) & H1MASK;                                    \
            }                                                                \
            if (_sl >= 0) {                                                  \
                int _e = (ee);                                               \
                int _r = is32 ? ei32[_e] : (int)ei64[_e];                    \
                int _ps = atomicAdd(&g_l1e_count, 1);                        \
                if (_ps < MAX_L1E) {                                         \
                    g_l1_row[_ps] = _r; g_l1_cslot[_ps] = _sl;               \
                    g_l1_w[_ps] = ew[_e];                                    \
                    rtab_insert(_r);                                         \
                }                                                            \
            }                                                                \
        } while (0)
        if (is32) {
            const int4* col4 = (const int4*)(ei32 + E);
            int nvec = E >> 2;
            for (int v = gtid; v < nvec; v += gsz) {
                int4 c4 = col4[v]; int e = v * 4;
                DO_B(c4.x, e); DO_B(c4.y, e + 1); DO_B(c4.z, e + 2); DO_B(c4.w, e + 3);
            }
            for (int e = (nvec << 2) + gtid; e < E; e += gsz) DO_B(ei32[E + e], e);
        } else {
            const longlong2* col2 = (const longlong2*)(ei64 + E);
            int nvec = E >> 1;
            for (int v = gtid; v < nvec; v += gsz) {
                longlong2 c2 = col2[v]; int e = v * 2;
                DO_B((int)c2.x, e); DO_B((int)c2.y, e + 1);
            }
            for (int e = (nvec << 1) + gtid; e < E; e += gsz) DO_B((int)ei64[E + e], e);
        }
#undef DO_B
    }
    GSYNC();

    // ============ phase 3: passC (degrees of R nodes) =====================
    {
        int* rt = (int*)sbuf64;                           // 16 KB
        for (int i = tid; i < RTBL; i += TPB) rt[i] = g_rtab[i];
        __syncthreads();
        int is32 = g_is32;
#define DO_C(cc, ee) do {                                                    \
            int _c = (cc);                                                   \
            unsigned _ix = hsh(_c) & RMASK;                                  \
            for (int _p = 0; _p < RTBL; _p++) {                              \
                int _v = rt[_ix];                                            \
                if (_v == 0) break;                                          \
                if (_v == _c + 1) { atomicAdd(&g_deg[_c], ew[(ee)]); break; }\
                _ix = (_ix + 1) & RMASK;                                     \
            }                                                                \
        } while (0)
        if (is32) {
            const int4* col4 = (const int4*)(ei32 + E);
            int nvec = E >> 2;
            for (int v = gtid; v < nvec; v += gsz) {
                int4 c4 = col4[v]; int e = v * 4;
                DO_C(c4.x, e); DO_C(c4.y, e + 1); DO_C(c4.z, e + 2); DO_C(c4.w, e + 3);
            }
            for (int e = (nvec << 2) + gtid; e < E; e += gsz) DO_C(ei32[E + e], e);
        } else {
            const longlong2* col2 = (const longlong2*)(ei64 + E);
            int nvec = E >> 1;
            for (int v = gtid; v < nvec; v += gsz) {
                longlong2 c2 = col2[v]; int e = v * 2;
                DO_C((int)c2.x, e); DO_C((int)c2.y, e + 1);
            }
            for (int e = (nvec << 1) + gtid; e < E; e += gsz) DO_C((int)ei64[E + e], e);
        }
#undef DO_C
    }
    GSYNC();
    // ----- last full barrier; blocks >= 32 reset hash tables and exit -----
    if (bid >= 32) {
        int base = (bid - 32) * TPB + tid;
        int stride = (GRID - 32) * TPB;
        for (int i = base; i < H1TBL; i += stride) g_h1pack[i] = 0;
        for (int i = base; i < RTBL;  i += stride) g_rtab[i]  = 0;
        return;
    }

    // ============ phase 4: layer 1 (blocks 0..31) =========================
    {
        float* acc = (float*)sbuf64;                      // 128 floats
        int ns1 = min(g_s1_count, MAX_S1);
        int nl1 = min(g_l1e_count, MAX_L1E);
        for (int s = bid; s < ns1; s += 32) {
            int node = g_s1_node[s];
            if (node < 0) continue;                        // wasted slot
            float degc = g_deg[node] + 1.0f;
            float dc = rsqrtf(degc);
            if (tid < 128) acc[tid] = x[(size_t)node * 128 + tid] / degc;
            __syncthreads();
            for (int e = 0; e < nl1; e++) {
                if (g_l1_cslot[e] == s) {
                    int r = g_l1_row[e];
                    float norm = g_l1_w[e] * rsqrtf(g_deg[r] + 1.0f) * dc;
                    if (tid < 128) acc[tid] += norm * x[(size_t)r * 128 + tid];
                }
            }
            __syncthreads();
            if (tid < 256) {
                float aj = b1[tid];
#pragma unroll 8
                for (int k = 0; k < 128; k++) aj += acc[k] * W1[k * 256 + tid];
                g_h1[s * 256 + tid] = fmaxf(aj, 0.0f);
            }
            __syncthreads();
        }
    }
    MARRIVE(0, 32, mp0);
    if (bid >= 8) return;

    // ============ phase 5: layer 2 (blocks 0..7, j-chunks of 32) ==========
    MWAIT(0, mp0);
    {
        float* agg   = (float*)sbuf64;                    // 256
        float* spart = agg + 256;                         // 256
        int ns2 = min(g_s2_count, MAX_S2);
        int nl2 = min(g_l2e_count, MAX_L2E);
        int j0 = bid * 32;
        float zacc = 0.0f;                                // tid<32 only
        for (int s = 0; s < ns2; s++) {
            int cnode = g_s2_node[s];
            float degc = g_deg[cnode] + 1.0f;
            float dc = rsqrtf(degc);
            if (tid < 256) {
                int cs1 = g_s2_s1slot[s];
                float a = g_h1[cs1 * 256 + tid] / degc;
                for (int e = 0; e < nl2; e++) {
                    if (g_l2_cslot[e] == s) {
                        int rnode = g_l2_row[e];
                        float norm = g_l2_w[e] * rsqrtf(g_deg[rnode] + 1.0f) * dc;
                        a += norm * g_h1[g_l2_rslot[e] * 256 + tid];
                    }
                }
                agg[tid] = a;
            }
            __syncthreads();
            if (tid < 256) {
                int kc = tid >> 5, j = tid & 31;
                float p = 0.0f;
#pragma unroll 8
                for (int k = kc * 32; k < kc * 32 + 32; k++)
                    p += agg[k] * W2[k * 256 + j0 + j];
                spart[tid] = p;
            }
            __syncthreads();
            if (tid < 32) {
                float sum = b2[j0 + tid];
#pragma unroll
                for (int c = 0; c < 8; c++) sum += spart[c * 32 + tid];
                zacc += g_s2_val[s] * fmaxf(sum, 0.0f);
            }
            __syncthreads();
        }
        if (tid < 32) g_z[j0 + tid] = zacc;               // overwrite, no reset
    }
    MARRIVE(1, 8, mp1);

    // ============ phase 6: head GEMV1 480->512 (blocks 0..7) ==============
    MWAIT(1, mp1);
    {
        float* feat  = (float*)sbuf64;                    // 480
        float* spart = feat + 480;                        // 512
        int is32 = g_is32;
        int wtI  = is32 ? ((const int*)wt_idx)[0]  : (int)wt_idx[0];
        int mutI = is32 ? ((const int*)mut_idx)[0] : (int)mut_idx[0];
        if (tid < 256) feat[tid] = g_z[tid];
        else if (tid < 480) {
            int j = tid - 256;
            float v;
            if (j < 64)       v = aa_emb[wtI  * 64 + j];
            else if (j < 128) v = aa_emb[mutI * 64 + (j - 64)];
            else if (j < 192) v = aa_emb[mutI * 64 + (j - 128)] -
                                  aa_emb[wtI  * 64 + (j - 128)];
            else {
                unsigned int low = (unsigned int)(g_argmax_key & 0xFFFFFFFFull);
                int pos = (int)(0xFFFFFFFFu - low);
                if (pos < 0) pos = 0;
                if (pos > max_pos - 1) pos = max_pos - 1;
                v = pos_emb[pos * 32 + (j - 192)];
            }
            feat[tid] = v;
        }
        __syncthreads();
        int kc = tid >> 6, jj = tid & 63;                 // 8 k-chunks x 64 outs
        int j  = bid * 64 + jj;
        float p = 0.0f;
#pragma unroll 10
        for (int k = kc * 60; k < kc * 60 + 60; k++)
            p += feat[k] * Wh1[k * 512 + j];
        spart[tid] = p;
        __syncthreads();
        if (tid < 64) {
            float sum = bh1[bid * 64 + tid];
#pragma unroll
            for (int c = 0; c < 8; c++) sum += spart[c * 64 + tid];
            g_f1[bid * 64 + tid] = fmaxf(sum, 0.0f);
        }
    }
    MARRIVE(2, 8, mp2);

    if (bid == 1) {           // reset counters for next replay (after M2 flip)
        MWAIT(2, mp2);
        if (tid == 0) {
            g_s2_count = 0; g_l2e_count = 0; g_l1e_count = 0;
            g_s1_count = 0; g_r_count = 0; g_is32 = 0;
            g_argmax_key = 0ull;
        }
        return;
    }
    if (bid != 0) return;

    // ============ phase 7: head GEMV2 + final dot (block 0) ===============
    MWAIT(2, mp2);
    {
        float* sf1   = (float*)sbuf64;                    // 512
        float* spart = sf1 + 512;                         // 512
        sf1[tid] = g_f1[tid];
        __syncthreads();
        int kc = tid >> 7, j = tid & 127;                 // 4 k-chunks x 128
        float p = 0.0f;
#pragma unroll 8
        for (int k = kc * 128; k < kc * 128 + 128; k++)
            p += sf1[k] * Wh2[k * 128 + j];
        spart[kc * 128 + j] = p;
        __syncthreads();
        float* f2 = spart;                                // reuse low 128
        if (tid < 128) {
            float sum = bh2[tid] + spart[tid] + spart[128 + tid] +
                        spart[256 + tid] + spart[384 + tid];
            f2[tid] = fmaxf(sum, 0.0f) * Wh3[tid];
        }
        __syncthreads();
        if (tid < 64) f2[tid] += f2[tid + 64];
        __syncthreads();
        if (tid < 32) {
            float v = f2[tid] + f2[tid + 32];
            for (int o = 16; o > 0; o >>= 1) v += __shfl_down_sync(0xFFFFFFFFu, v, o);
            if (tid == 0) out[0] = v + bh3[0];
        }
    }
#undef GSYNC
#undef MARRIVE
#undef MWAIT
}

// ---------------------------------------------------------------------------
extern "C" void kernel_launch(void* const* d_in, const int* in_sizes, int n_in,
                              void* d_out, int out_size) {
    const float*     x       = (const float*)d_in[0];
    const long long* ei      = (const long long*)d_in[1];
    const float*     ew      = (const float*)d_in[2];
    const float*     mask    = (const float*)d_in[3];
    const long long* wt_idx  = (const long long*)d_in[4];
    const long long* mut_idx = (const long long*)d_in[5];
    const float*     W1      = (const float*)d_in[6];
    const float*     b1      = (const float*)d_in[7];
    const float*     W2      = (const float*)d_in[8];
    const float*     b2      = (const float*)d_in[9];
    const float*     aa_emb  = (const float*)d_in[10];
    const float*     pos_emb = (const float*)d_in[11];
    const float*     Wh1     = (const float*)d_in[12];
    const float*     bh1     = (const float*)d_in[13];
    const float*     Wh2     = (const float*)d_in[14];
    const float*     bh2     = (const float*)d_in[15];
    const float*     Wh3     = (const float*)d_in[16];
    const float*     bh3     = (const float*)d_in[17];
    float*           out     = (float*)d_out;

    int n       = in_sizes[3];
    int E       = in_sizes[2];
    int max_pos = in_sizes[11] / 32;

    hgnn_fused<<<GRID, TPB>>>(x, ei, ew, mask, wt_idx, mut_idx,
                              W1, b1, W2, b2, aa_emb, pos_emb,
                              Wh1, bh1, Wh2, bh2, Wh3, bh3,
                              out, n, E, max_pos);
}

// round 6
// speedup vs baseline: 1.7077x; 1.0486x over previous
#include <cuda_runtime.h>
#include <cuda_bf16.h>

// ---------------------------------------------------------------------------
// HGNN, 5-kernel pipeline: mask -> passA(+S1 build) -> passB -> passC -> tail.
// Hash probes via L1-cached global loads (tables read-only during each pass).
// ---------------------------------------------------------------------------

#define NMAX     100000
#define MAX_S2   32
#define MAX_L2E  2048
#define MAX_S1   (MAX_L2E + MAX_S2 + 64)
#define H1TBL    4096
#define H1MASK   4095
#define RTBL     4096
#define RMASK    4095
#define RCAP     3500
#define MAX_L1E  32768

__device__ float g_deg[NMAX];                 // lazily zeroed at rtab_insert
__device__ int   g_h1pack[H1TBL];             // (slot<<17)|(node+1); 0 empty
__device__ int   g_rtab[RTBL];                // node+1; 0 empty
__device__ int   g_s2_node[MAX_S2];
__device__ float g_s2_val[MAX_S2];
__device__ int   g_s2_s1slot[MAX_S2];
__device__ int   g_l2_row[MAX_L2E];
__device__ int   g_l2_cslot[MAX_L2E];
__device__ int   g_l2_rslot[MAX_L2E];
__device__ float g_l2_w[MAX_L2E];
__device__ int   g_s1_node[MAX_S1];           // -1 = wasted slot
__device__ int   g_l1_row[MAX_L1E];
__device__ int   g_l1_cslot[MAX_L1E];
__device__ float g_l1_w[MAX_L1E];
__device__ float g_h1[MAX_S1 * 256];
__device__ float g_z[256];
__device__ float g_f1[512];
__device__ int   g_s2_count, g_l2e_count, g_l1e_count, g_s1_count, g_r_count, g_is32;
__device__ unsigned long long g_argmax_key;
__device__ int               g_marr[3];
__device__ volatile unsigned g_mph[3];        // monotonic mini phases

__device__ __forceinline__ unsigned hsh(int v) {
    return ((unsigned)v * 2654435761u) >> 13;
}

__device__ void rtab_insert(int node) {
    if (g_r_count >= RCAP) return;
    unsigned idx = hsh(node) & RMASK;
    for (int p = 0; p < RTBL; p++) {
        int cur = atomicCAS(&g_rtab[idx], 0, node + 1);
        if (cur == 0) { g_deg[node] = 0.0f; atomicAdd(&g_r_count, 1); return; }
        if (cur == node + 1) return;
        idx = (idx + 1) & RMASK;
    }
}

// Insert node into S1 hash; returns dense slot. Slot packed with node in one
// CAS word so readers always see complete pairs. Lost races burn a slot
// (marked -1 in g_s1_node).
__device__ int h1_insert(int node) {
    unsigned idx = hsh(node) & H1MASK;
    int myslot = -1;
    for (int p = 0; p < H1TBL; p++) {
        int v = g_h1pack[idx];
        if (v != 0) {
            if ((v & 0x1FFFF) == node + 1) {
                if (myslot >= 0) g_s1_node[myslot] = -1;
                return v >> 17;
            }
        } else {
            if (myslot < 0) {
                myslot = atomicAdd(&g_s1_count, 1);
                if (myslot >= MAX_S1) return -1;
            }
            int cur = atomicCAS(&g_h1pack[idx], 0, (myslot << 17) | (node + 1));
            if (cur == 0) {
                g_s1_node[myslot] = node;
                rtab_insert(node);
                return myslot;
            }
            if ((cur & 0x1FFFF) == node + 1) {
                g_s1_node[myslot] = -1;
                return cur >> 17;
            }
        }
        idx = (idx + 1) & H1MASK;
    }
    return -1;
}

// ===========================================================================
// k0: dtype detect (warp ballot) + mask scan (S2 + argmax)
__global__ void k0_mask(const float* __restrict__ mask,
                        const long long* __restrict__ ei64, int n, int E) {
    __shared__ unsigned long long sk[256];
    int i = blockIdx.x * blockDim.x + threadIdx.x;
    int lim = E < 1024 ? E : 1024;
    if (i < lim) {
        long long v = ei64[i];
        bool bad = (v < 0 || v >= (long long)n);
        if (__any_sync(__activemask(), bad)) {
            if ((threadIdx.x & 31) == 0) g_is32 = 1;
        }
    }
    unsigned long long key = 0ull;
    if (i < n) {
        float m = mask[i];
        if (m != 0.0f) {
            int slot = atomicAdd(&g_s2_count, 1);
            if (slot < MAX_S2) {
                g_s2_node[slot] = i; g_s2_val[slot] = m;
                g_s2_s1slot[slot] = h1_insert(i);
            }
        }
        unsigned int b  = __float_as_uint(m);
        unsigned int ub = (b & 0x80000000u) ? ~b : (b | 0x80000000u);
        key = (((unsigned long long)ub) << 32) |
              (unsigned long long)(0xFFFFFFFFu - (unsigned)i);
    }
    sk[threadIdx.x] = key;
    __syncthreads();
    for (int o = 128; o > 0; o >>= 1) {
        if (threadIdx.x < o) {
            unsigned long long a = sk[threadIdx.x], b2 = sk[threadIdx.x + o];
            sk[threadIdx.x] = (a > b2) ? a : b2;
        }
        __syncthreads();
    }
    if (threadIdx.x == 0 && sk[0] != 0ull) atomicMax(&g_argmax_key, sk[0]);
}

// ===========================================================================
// k1: passA — edges into S2; record L2 edges; inline S1 hash build
__global__ void k1_passA(const long long* __restrict__ ei64,
                         const float* __restrict__ ew, int E) {
    __shared__ int s2n[MAX_S2];
    __shared__ int ns2_s, is32_s;
    if (threadIdx.x == 0) { ns2_s = min(g_s2_count, MAX_S2); is32_s = g_is32; }
    __syncthreads();
    int ns2 = ns2_s, is32 = is32_s;
    if (threadIdx.x < ns2) s2n[threadIdx.x] = g_s2_node[threadIdx.x];
    __syncthreads();
    const int* ei32 = (const int*)ei64;
    int gsz  = gridDim.x * blockDim.x;
    int gtid = blockIdx.x * blockDim.x + threadIdx.x;
#define DO_A(cc, ee) do {                                                    \
        int _c = (cc); int _ms = -1;                                         \
        for (int _j = 0; _j < ns2; _j++) if (_c == s2n[_j]) _ms = _j;        \
        if (_ms >= 0) {                                                      \
            int _e = (ee);                                                   \
            int _r = is32 ? ei32[_e] : (int)ei64[_e];                        \
            int _sl = atomicAdd(&g_l2e_count, 1);                            \
            if (_sl < MAX_L2E) {                                             \
                g_l2_row[_sl] = _r; g_l2_cslot[_sl] = _ms;                   \
                g_l2_w[_sl] = ew[_e];                                        \
                g_l2_rslot[_sl] = h1_insert(_r);                             \
            }                                                                \
        }                                                                    \
    } while (0)
    if (is32 && ((E & 3) == 0)) {
        const int4* col4 = (const int4*)(ei32 + E);
        int nvec = E >> 2;
        for (int v = gtid; v < nvec; v += gsz) {
            int4 c4 = col4[v]; int e = v * 4;
            DO_A(c4.x, e); DO_A(c4.y, e + 1); DO_A(c4.z, e + 2); DO_A(c4.w, e + 3);
        }
    } else if (!is32 && ((E & 1) == 0)) {
        const longlong2* col2 = (const longlong2*)(ei64 + E);
        int nvec = E >> 1;
        for (int v = gtid; v < nvec; v += gsz) {
            longlong2 c2 = col2[v]; int e = v * 2;
            DO_A((int)c2.x, e); DO_A((int)c2.y, e + 1);
        }
    } else {
        for (int e = gtid; e < E; e += gsz)
            DO_A(is32 ? ei32[E + e] : (int)ei64[E + e], e);
    }
#undef DO_A
}

// ===========================================================================
// k2: passB — edges into S1 (probe global H1 hash, L1-cached); record L1 edges
__global__ void k2_passB(const long long* __restrict__ ei64,
                         const float* __restrict__ ew, int E) {
    const int* ei32 = (const int*)ei64;
    int is32 = g_is32;
    int gsz  = gridDim.x * blockDim.x;
    int gtid = blockIdx.x * blockDim.x + threadIdx.x;
#define DO_B(cc, ee) do {                                                    \
        int _c = (cc);                                                       \
        unsigned _ix = hsh(_c) & H1MASK; int _sl = -1;                       \
        for (int _p = 0; _p < H1TBL; _p++) {                                 \
            int _v = __ldg(&g_h1pack[_ix]);                                  \
            if (_v == 0) break;                                              \
            if ((_v & 0x1FFFF) == _c + 1) { _sl = _v >> 17; break; }         \
            _ix = (_ix + 1) & H1MASK;                                        \
        }                                                                    \
        if (_sl >= 0) {                                                      \
            int _e = (ee);                                                   \
            int _r = is32 ? ei32[_e] : (int)ei64[_e];                        \
            int _ps = atomicAdd(&g_l1e_count, 1);                            \
            if (_ps < MAX_L1E) {                                             \
                g_l1_row[_ps] = _r; g_l1_cslot[_ps] = _sl;                   \
                g_l1_w[_ps] = ew[_e];                                        \
                rtab_insert(_r);                                             \
            }                                                                \
        }                                                                    \
    } while (0)
    if (is32 && ((E & 3) == 0)) {
        const int4* col4 = (const int4*)(ei32 + E);
        int nvec = E >> 2;
        for (int v = gtid; v < nvec; v += gsz) {
            int4 c4 = col4[v]; int e = v * 4;
            DO_B(c4.x, e); DO_B(c4.y, e + 1); DO_B(c4.z, e + 2); DO_B(c4.w, e + 3);
        }
    } else if (!is32 && ((E & 1) == 0)) {
        const longlong2* col2 = (const longlong2*)(ei64 + E);
        int nvec = E >> 1;
        for (int v = gtid; v < nvec; v += gsz) {
            longlong2 c2 = col2[v]; int e = v * 2;
            DO_B((int)c2.x, e); DO_B((int)c2.y, e + 1);
        }
    } else {
        for (int e = gtid; e < E; e += gsz)
            DO_B(is32 ? ei32[E + e] : (int)ei64[E + e], e);
    }
#undef DO_B
}

// ===========================================================================
// k3: passC — degrees of R nodes (probe global R hash, L1-cached)
__global__ void k3_passC(const long long* __restrict__ ei64,
                         const float* __restrict__ ew, int E) {
    const int* ei32 = (const int*)ei64;
    int is32 = g_is32;
    int gsz  = gridDim.x * blockDim.x;
    int gtid = blockIdx.x * blockDim.x + threadIdx.x;
#define DO_C(cc, ee) do {                                                    \
        int _c = (cc);                                                       \
        unsigned _ix = hsh(_c) & RMASK;                                      \
        for (int _p = 0; _p < RTBL; _p++) {                                  \
            int _v = __ldg(&g_rtab[_ix]);                                    \
            if (_v == 0) break;                                              \
            if (_v == _c + 1) { atomicAdd(&g_deg[_c], ew[(ee)]); break; }    \
            _ix = (_ix + 1) & RMASK;                                         \
        }                                                                    \
    } while (0)
    if (is32 && ((E & 3) == 0)) {
        const int4* col4 = (const int4*)(ei32 + E);
        int nvec = E >> 2;
        for (int v = gtid; v < nvec; v += gsz) {
            int4 c4 = col4[v]; int e = v * 4;
            DO_C(c4.x, e); DO_C(c4.y, e + 1); DO_C(c4.z, e + 2); DO_C(c4.w, e + 3);
        }
    } else if (!is32 && ((E & 1) == 0)) {
        const longlong2* col2 = (const longlong2*)(ei64 + E);
        int nvec = E >> 1;
        for (int v = gtid; v < nvec; v += gsz) {
            longlong2 c2 = col2[v]; int e = v * 2;
            DO_C((int)c2.x, e); DO_C((int)c2.y, e + 1);
        }
    } else {
        for (int e = gtid; e < E; e += gsz)
            DO_C(is32 ? ei32[E + e] : (int)ei64[E + e], e);
    }
#undef DO_C
}

// ===========================================================================
// k4: tail — layer1 (32 blocks) -> layer2 (8) -> GEMV1 (8) -> GEMV2 (1)
#define TTPB 512
__global__ __launch_bounds__(TTPB) void k4_tail(
    const float* __restrict__ x,
    const long long* __restrict__ wt_idx,
    const long long* __restrict__ mut_idx,
    const float* __restrict__ W1, const float* __restrict__ b1,
    const float* __restrict__ W2, const float* __restrict__ b2,
    const float* __restrict__ aa_emb, const float* __restrict__ pos_emb,
    const float* __restrict__ Wh1, const float* __restrict__ bh1,
    const float* __restrict__ Wh2, const float* __restrict__ bh2,
    const float* __restrict__ Wh3, const float* __restrict__ bh3,
    float* __restrict__ out, int max_pos)
{
    __shared__ float sbuf[1024];
    const int tid = threadIdx.x;
    const int bid = blockIdx.x;
    unsigned mp0 = g_mph[0], mp1 = g_mph[1], mp2 = g_mph[2];

#define MARRIVE(id, total, mpv) do {                                         \
        __syncthreads();                                                     \
        if (tid == 0) {                                                      \
            __threadfence();                                                 \
            if (atomicAdd(&g_marr[id], 1) == (total) - 1) {                  \
                g_marr[id] = 0; __threadfence(); g_mph[id] = (mpv) + 1u;     \
            }                                                                \
        }                                                                    \
    } while (0)
#define MWAIT(id, mpv) do {                                                  \
        if (tid == 0) { while (g_mph[id] == (mpv)) { } __threadfence(); }    \
        __syncthreads();                                                     \
    } while (0)

    // ---- layer 1 (blocks 0..31) ----
    {
        float* acc = sbuf;
        int ns1 = min(g_s1_count, MAX_S1);
        int nl1 = min(g_l1e_count, MAX_L1E);
        for (int s = bid; s < ns1; s += 32) {
            int node = g_s1_node[s];
            if (node < 0) continue;
            float degc = g_deg[node] + 1.0f;
            float dc = rsqrtf(degc);
            if (tid < 128) acc[tid] = x[(size_t)node * 128 + tid] / degc;
            __syncthreads();
            for (int e = 0; e < nl1; e++) {
                if (g_l1_cslot[e] == s) {
                    int r = g_l1_row[e];
                    float norm = g_l1_w[e] * rsqrtf(g_deg[r] + 1.0f) * dc;
                    if (tid < 128) acc[tid] += norm * x[(size_t)r * 128 + tid];
                }
            }
            __syncthreads();
            if (tid < 256) {
                float aj = b1[tid];
#pragma unroll 8
                for (int k = 0; k < 128; k++) aj += acc[k] * W1[k * 256 + tid];
                g_h1[s * 256 + tid] = fmaxf(aj, 0.0f);
            }
            __syncthreads();
        }
    }
    MARRIVE(0, 32, mp0);
    if (bid >= 8) {
        // blocks 8..31: reset hash tables (not needed by later tail phases)
        int base = (bid - 8) * TTPB + tid;
        int stride = 24 * TTPB;
        for (int i = base; i < H1TBL; i += stride) g_h1pack[i] = 0;
        for (int i = base; i < RTBL;  i += stride) g_rtab[i]  = 0;
        return;
    }

    // ---- layer 2 (blocks 0..7, 32 outputs each) ----
    MWAIT(0, mp0);
    {
        float* agg   = sbuf;           // 256
        float* spart = sbuf + 256;     // 256
        int ns2 = min(g_s2_count, MAX_S2);
        int nl2 = min(g_l2e_count, MAX_L2E);
        int j0 = bid * 32;
        float zacc = 0.0f;
        for (int s = 0; s < ns2; s++) {
            int cnode = g_s2_node[s];
            float degc = g_deg[cnode] + 1.0f;
            float dc = rsqrtf(degc);
            if (tid < 256) {
                int cs1 = g_s2_s1slot[s];
                float a = (cs1 >= 0) ? g_h1[cs1 * 256 + tid] / degc : 0.0f;
                for (int e = 0; e < nl2; e++) {
                    if (g_l2_cslot[e] == s) {
                        int rslot = g_l2_rslot[e];
                        if (rslot >= 0) {
                            int rnode = g_l2_row[e];
                            float norm = g_l2_w[e] * rsqrtf(g_deg[rnode] + 1.0f) * dc;
                            a += norm * g_h1[rslot * 256 + tid];
                        }
                    }
                }
                agg[tid] = a;
            }
            __syncthreads();
            if (tid < 256) {
                int kc = tid >> 5, j = tid & 31;
                float p = 0.0f;
#pragma unroll 8
                for (int k = kc * 32; k < kc * 32 + 32; k++)
                    p += agg[k] * W2[k * 256 + j0 + j];
                spart[tid] = p;
            }
            __syncthreads();
            if (tid < 32) {
                float sum = b2[j0 + tid];
#pragma unroll
                for (int c = 0; c < 8; c++) sum += spart[c * 32 + tid];
                zacc += g_s2_val[s] * fmaxf(sum, 0.0f);
            }
            __syncthreads();
        }
        if (tid < 32) g_z[j0 + tid] = zacc;
    }
    MARRIVE(1, 8, mp1);

    // ---- head GEMV1 480->512 (blocks 0..7, 64 outputs each) ----
    MWAIT(1, mp1);
    {
        float* feat  = sbuf;           // 480
        float* spart = sbuf + 480;     // 512
        int is32 = g_is32;
        int wtI  = is32 ? ((const int*)wt_idx)[0]  : (int)wt_idx[0];
        int mutI = is32 ? ((const int*)mut_idx)[0] : (int)mut_idx[0];
        if (tid < 256) feat[tid] = g_z[tid];
        else if (tid < 480) {
            int j = tid - 256;
            float v;
            if (j < 64)       v = aa_emb[wtI  * 64 + j];
            else if (j < 128) v = aa_emb[mutI * 64 + (j - 64)];
            else if (j < 192) v = aa_emb[mutI * 64 + (j - 128)] -
                                  aa_emb[wtI  * 64 + (j - 128)];
            else {
                unsigned int low = (unsigned int)(g_argmax_key & 0xFFFFFFFFull);
                int pos = (int)(0xFFFFFFFFu - low);
                if (pos < 0) pos = 0;
                if (pos > max_pos - 1) pos = max_pos - 1;
                v = pos_emb[pos * 32 + (j - 192)];
            }
            feat[tid] = v;
        }
        __syncthreads();
        int kc = tid >> 6, jj = tid & 63;
        int j  = bid * 64 + jj;
        float p = 0.0f;
#pragma unroll 10
        for (int k = kc * 60; k < kc * 60 + 60; k++)
            p += feat[k] * Wh1[k * 512 + j];
        spart[tid] = p;
        __syncthreads();
        if (tid < 64) {
            float sum = bh1[bid * 64 + tid];
#pragma unroll
            for (int c = 0; c < 8; c++) sum += spart[c * 64 + tid];
            g_f1[bid * 64 + tid] = fmaxf(sum, 0.0f);
        }
    }
    MARRIVE(2, 8, mp2);

    if (bid == 1) {
        MWAIT(2, mp2);
        if (tid == 0) {
            g_s2_count = 0; g_l2e_count = 0; g_l1e_count = 0;
            g_s1_count = 0; g_r_count = 0; g_is32 = 0;
            g_argmax_key = 0ull;
        }
        return;
    }
    if (bid != 0) return;

    // ---- head GEMV2 + final dot (block 0) ----
    MWAIT(2, mp2);
    {
        float* sf1   = sbuf;           // 512
        float* spart = sbuf + 512;     // 512
        sf1[tid] = g_f1[tid];
        __syncthreads();
        int kc = tid >> 7, j = tid & 127;
        float p = 0.0f;
#pragma unroll 8
        for (int k = kc * 128; k < kc * 128 + 128; k++)
            p += sf1[k] * Wh2[k * 128 + j];
        spart[kc * 128 + j] = p;
        __syncthreads();
        float* f2 = spart;
        if (tid < 128) {
            float sum = bh2[tid] + spart[tid] + spart[128 + tid] +
                        spart[256 + tid] + spart[384 + tid];
            f2[tid] = fmaxf(sum, 0.0f) * Wh3[tid];
        }
        __syncthreads();
        if (tid < 64) f2[tid] += f2[tid + 64];
        __syncthreads();
        if (tid < 32) {
            float v = f2[tid] + f2[tid + 32];
            for (int o = 16; o > 0; o >>= 1) v += __shfl_down_sync(0xFFFFFFFFu, v, o);
            if (tid == 0) out[0] = v + bh3[0];
        }
    }
#undef MARRIVE
#undef MWAIT
}

// ---------------------------------------------------------------------------
extern "C" void kernel_launch(void* const* d_in, const int* in_sizes, int n_in,
                              void* d_out, int out_size) {
    const float*     x       = (const float*)d_in[0];
    const long long* ei      = (const long long*)d_in[1];
    const float*     ew      = (const float*)d_in[2];
    const float*     mask    = (const float*)d_in[3];
    const long long* wt_idx  = (const long long*)d_in[4];
    const long long* mut_idx = (const long long*)d_in[5];
    const float*     W1      = (const float*)d_in[6];
    const float*     b1      = (const float*)d_in[7];
    const float*     W2      = (const float*)d_in[8];
    const float*     b2      = (const float*)d_in[9];
    const float*     aa_emb  = (const float*)d_in[10];
    const float*     pos_emb = (const float*)d_in[11];
    const float*     Wh1     = (const float*)d_in[12];
    const float*     bh1     = (const float*)d_in[13];
    const float*     Wh2     = (const float*)d_in[14];
    const float*     bh2     = (const float*)d_in[15];
    const float*     Wh3     = (const float*)d_in[16];
    const float*     bh3     = (const float*)d_in[17];
    float*           out     = (float*)d_out;

    int n       = in_sizes[3];
    int E       = in_sizes[2];
    int max_pos = in_sizes[11] / 32;

    k0_mask <<<(n + 255) / 256, 256>>>(mask, ei, n, E);
    k1_passA<<<592, 256>>>(ei, ew, E);
    k2_passB<<<592, 256>>>(ei, ew, E);
    k3_passC<<<592, 256>>>(ei, ew, E);
    k4_tail <<<32, TTPB>>>(x, wt_idx, mut_idx, W1, b1, W2, b2,
                           aa_emb, pos_emb, Wh1, bh1, Wh2, bh2, Wh3, bh3,
                           out, max_pos);
}

// round 7
// speedup vs baseline: 2.0251x; 1.1859x over previous
#include <cuda_runtime.h>
#include <cuda_bf16.h>

// ---------------------------------------------------------------------------
// HGNN, 5-kernel pipeline v2: pass kernels at 8 blocks/SM (1184x256),
// layer1 with parallel edge-match scan. Hash probes via L1-cached loads.
// ---------------------------------------------------------------------------

#define NMAX     100000
#define MAX_S2   32
#define MAX_L2E  2048
#define MAX_S1   (MAX_L2E + MAX_S2 + 64)
#define H1TBL    4096
#define H1MASK   4095
#define RTBL     4096
#define RMASK    4095
#define RCAP     3500
#define MAX_L1E  32768
#define GRIDP    1184

__device__ float g_deg[NMAX];                 // lazily zeroed at rtab_insert
__device__ int   g_h1pack[H1TBL];             // (slot<<17)|(node+1); 0 empty
__device__ int   g_rtab[RTBL];                // node+1; 0 empty
__device__ int   g_s2_node[MAX_S2];
__device__ float g_s2_val[MAX_S2];
__device__ int   g_s2_s1slot[MAX_S2];
__device__ int   g_l2_row[MAX_L2E];
__device__ int   g_l2_cslot[MAX_L2E];
__device__ int   g_l2_rslot[MAX_L2E];
__device__ float g_l2_w[MAX_L2E];
__device__ int   g_s1_node[MAX_S1];           // -1 = wasted slot
__device__ int   g_l1_row[MAX_L1E];
__device__ int   g_l1_cslot[MAX_L1E];
__device__ float g_l1_w[MAX_L1E];
__device__ float g_h1[MAX_S1 * 256];
__device__ float g_z[256];
__device__ float g_f1[512];
__device__ int   g_s2_count, g_l2e_count, g_l1e_count, g_s1_count, g_r_count, g_is32;
__device__ unsigned long long g_argmax_key;
__device__ int               g_marr[3];
__device__ volatile unsigned g_mph[3];        // monotonic mini phases

__device__ __forceinline__ unsigned hsh(int v) {
    return ((unsigned)v * 2654435761u) >> 13;
}

__device__ void rtab_insert(int node) {
    if (g_r_count >= RCAP) return;
    unsigned idx = hsh(node) & RMASK;
    for (int p = 0; p < RTBL; p++) {
        int cur = atomicCAS(&g_rtab[idx], 0, node + 1);
        if (cur == 0) { g_deg[node] = 0.0f; atomicAdd(&g_r_count, 1); return; }
        if (cur == node + 1) return;
        idx = (idx + 1) & RMASK;
    }
}

// Insert node into S1 hash; returns dense slot. Slot packed with node in one
// CAS word so readers always see complete pairs. Lost races burn a slot.
__device__ int h1_insert(int node) {
    unsigned idx = hsh(node) & H1MASK;
    int myslot = -1;
    for (int p = 0; p < H1TBL; p++) {
        int v = g_h1pack[idx];
        if (v != 0) {
            if ((v & 0x1FFFF) == node + 1) {
                if (myslot >= 0) g_s1_node[myslot] = -1;
                return v >> 17;
            }
        } else {
            if (myslot < 0) {
                myslot = atomicAdd(&g_s1_count, 1);
                if (myslot >= MAX_S1) return -1;
            }
            int cur = atomicCAS(&g_h1pack[idx], 0, (myslot << 17) | (node + 1));
            if (cur == 0) {
                g_s1_node[myslot] = node;
                rtab_insert(node);
                return myslot;
            }
            if ((cur & 0x1FFFF) == node + 1) {
                g_s1_node[myslot] = -1;
                return cur >> 17;
            }
        }
        idx = (idx + 1) & H1MASK;
    }
    return -1;
}

// ===========================================================================
// k0: dtype detect (warp ballot) + mask scan (S2 + argmax)
__global__ void k0_mask(const float* __restrict__ mask,
                        const long long* __restrict__ ei64, int n, int E) {
    __shared__ unsigned long long sk[256];
    int i = blockIdx.x * blockDim.x + threadIdx.x;
    int lim = E < 1024 ? E : 1024;
    if (i < lim) {
        long long v = ei64[i];
        bool bad = (v < 0 || v >= (long long)n);
        if (__any_sync(__activemask(), bad)) {
            if ((threadIdx.x & 31) == 0) g_is32 = 1;
        }
    }
    unsigned long long key = 0ull;
    if (i < n) {
        float m = mask[i];
        if (m != 0.0f) {
            int slot = atomicAdd(&g_s2_count, 1);
            if (slot < MAX_S2) {
                g_s2_node[slot] = i; g_s2_val[slot] = m;
                g_s2_s1slot[slot] = h1_insert(i);
            }
        }
        unsigned int b  = __float_as_uint(m);
        unsigned int ub = (b & 0x80000000u) ? ~b : (b | 0x80000000u);
        key = (((unsigned long long)ub) << 32) |
              (unsigned long long)(0xFFFFFFFFu - (unsigned)i);
    }
    sk[threadIdx.x] = key;
    __syncthreads();
    for (int o = 128; o > 0; o >>= 1) {
        if (threadIdx.x < o) {
            unsigned long long a = sk[threadIdx.x], b2 = sk[threadIdx.x + o];
            sk[threadIdx.x] = (a > b2) ? a : b2;
        }
        __syncthreads();
    }
    if (threadIdx.x == 0 && sk[0] != 0ull) atomicMax(&g_argmax_key, sk[0]);
}

// ===========================================================================
// k1: passA — edges into S2; record L2 edges; inline S1 hash build
__global__ void k1_passA(const long long* __restrict__ ei64,
                         const float* __restrict__ ew, int E) {
    __shared__ int s2n[MAX_S2];
    __shared__ int ns2_s, is32_s;
    if (threadIdx.x == 0) { ns2_s = min(g_s2_count, MAX_S2); is32_s = g_is32; }
    __syncthreads();
    int ns2 = ns2_s, is32 = is32_s;
    if (threadIdx.x < ns2) s2n[threadIdx.x] = g_s2_node[threadIdx.x];
    __syncthreads();
    const int* ei32 = (const int*)ei64;
    int gsz  = gridDim.x * blockDim.x;
    int gtid = blockIdx.x * blockDim.x + threadIdx.x;
#define DO_A(cc, ee) do {                                                    \
        int _c = (cc); int _ms = -1;                                         \
        for (int _j = 0; _j < ns2; _j++) if (_c == s2n[_j]) _ms = _j;        \
        if (_ms >= 0) {                                                      \
            int _e = (ee);                                                   \
            int _r = is32 ? ei32[_e] : (int)ei64[_e];                        \
            int _sl = atomicAdd(&g_l2e_count, 1);                            \
            if (_sl < MAX_L2E) {                                             \
                g_l2_row[_sl] = _r; g_l2_cslot[_sl] = _ms;                   \
                g_l2_w[_sl] = ew[_e];                                        \
                g_l2_rslot[_sl] = h1_insert(_r);                             \
            }                                                                \
        }                                                                    \
    } while (0)
    if (is32 && ((E & 3) == 0)) {
        const int4* col4 = (const int4*)(ei32 + E);
        int nvec = E >> 2;
        for (int v = gtid; v < nvec; v += gsz) {
            int4 c4 = col4[v]; int e = v * 4;
            DO_A(c4.x, e); DO_A(c4.y, e + 1); DO_A(c4.z, e + 2); DO_A(c4.w, e + 3);
        }
    } else if (!is32 && ((E & 1) == 0)) {
        const longlong2* col2 = (const longlong2*)(ei64 + E);
        int nvec = E >> 1;
        for (int v = gtid; v < nvec; v += gsz) {
            longlong2 c2 = col2[v]; int e = v * 2;
            DO_A((int)c2.x, e); DO_A((int)c2.y, e + 1);
        }
    } else {
        for (int e = gtid; e < E; e += gsz)
            DO_A(is32 ? ei32[E + e] : (int)ei64[E + e], e);
    }
#undef DO_A
}

// ===========================================================================
// k2: passB — edges into S1 (probe global H1 hash); record L1 edges
__global__ void k2_passB(const long long* __restrict__ ei64,
                         const float* __restrict__ ew, int E) {
    const int* ei32 = (const int*)ei64;
    int is32 = g_is32;
    int gsz  = gridDim.x * blockDim.x;
    int gtid = blockIdx.x * blockDim.x + threadIdx.x;
#define DO_B(cc, ee) do {                                                    \
        int _c = (cc);                                                       \
        unsigned _ix = hsh(_c) & H1MASK; int _sl = -1;                       \
        for (int _p = 0; _p < H1TBL; _p++) {                                 \
            int _v = __ldg(&g_h1pack[_ix]);                                  \
            if (_v == 0) break;                                              \
            if ((_v & 0x1FFFF) == _c + 1) { _sl = _v >> 17; break; }         \
            _ix = (_ix + 1) & H1MASK;                                        \
        }                                                                    \
        if (_sl >= 0) {                                                      \
            int _e = (ee);                                                   \
            int _r = is32 ? ei32[_e] : (int)ei64[_e];                        \
            int _ps = atomicAdd(&g_l1e_count, 1);                            \
            if (_ps < MAX_L1E) {                                             \
                g_l1_row[_ps] = _r; g_l1_cslot[_ps] = _sl;                   \
                g_l1_w[_ps] = ew[_e];                                        \
                rtab_insert(_r);                                             \
            }                                                                \
        }                                                                    \
    } while (0)
    if (is32 && ((E & 3) == 0)) {
        const int4* col4 = (const int4*)(ei32 + E);
        int nvec = E >> 2;
        for (int v = gtid; v < nvec; v += gsz) {
            int4 c4 = col4[v]; int e = v * 4;
            DO_B(c4.x, e); DO_B(c4.y, e + 1); DO_B(c4.z, e + 2); DO_B(c4.w, e + 3);
        }
    } else if (!is32 && ((E & 1) == 0)) {
        const longlong2* col2 = (const longlong2*)(ei64 + E);
        int nvec = E >> 1;
        for (int v = gtid; v < nvec; v += gsz) {
            longlong2 c2 = col2[v]; int e = v * 2;
            DO_B((int)c2.x, e); DO_B((int)c2.y, e + 1);
        }
    } else {
        for (int e = gtid; e < E; e += gsz)
            DO_B(is32 ? ei32[E + e] : (int)ei64[E + e], e);
    }
#undef DO_B
}

// ===========================================================================
// k3: passC — degrees of R nodes (probe global R hash)
__global__ void k3_passC(const long long* __restrict__ ei64,
                         const float* __restrict__ ew, int E) {
    const int* ei32 = (const int*)ei64;
    int is32 = g_is32;
    int gsz  = gridDim.x * blockDim.x;
    int gtid = blockIdx.x * blockDim.x + threadIdx.x;
#define DO_C(cc, ee) do {                                                    \
        int _c = (cc);                                                       \
        unsigned _ix = hsh(_c) & RMASK;                                      \
        for (int _p = 0; _p < RTBL; _p++) {                                  \
            int _v = __ldg(&g_rtab[_ix]);                                    \
            if (_v == 0) break;                                              \
            if (_v == _c + 1) { atomicAdd(&g_deg[_c], ew[(ee)]); break; }    \
            _ix = (_ix + 1) & RMASK;                                         \
        }                                                                    \
    } while (0)
    if (is32 && ((E & 3) == 0)) {
        const int4* col4 = (const int4*)(ei32 + E);
        int nvec = E >> 2;
        for (int v = gtid; v < nvec; v += gsz) {
            int4 c4 = col4[v]; int e = v * 4;
            DO_C(c4.x, e); DO_C(c4.y, e + 1); DO_C(c4.z, e + 2); DO_C(c4.w, e + 3);
        }
    } else if (!is32 && ((E & 1) == 0)) {
        const longlong2* col2 = (const longlong2*)(ei64 + E);
        int nvec = E >> 1;
        for (int v = gtid; v < nvec; v += gsz) {
            longlong2 c2 = col2[v]; int e = v * 2;
            DO_C((int)c2.x, e); DO_C((int)c2.y, e + 1);
        }
    } else {
        for (int e = gtid; e < E; e += gsz)
            DO_C(is32 ? ei32[E + e] : (int)ei64[E + e], e);
    }
#undef DO_C
}

// ===========================================================================
// k4: tail — layer1 (32 blocks) -> layer2 (8) -> GEMV1 (8) -> GEMV2 (1)
#define TTPB  512
#define MAXM  512
__global__ __launch_bounds__(TTPB) void k4_tail(
    const float* __restrict__ x,
    const long long* __restrict__ wt_idx,
    const long long* __restrict__ mut_idx,
    const float* __restrict__ W1, const float* __restrict__ b1,
    const float* __restrict__ W2, const float* __restrict__ b2,
    const float* __restrict__ aa_emb, const float* __restrict__ pos_emb,
    const float* __restrict__ Wh1, const float* __restrict__ bh1,
    const float* __restrict__ Wh2, const float* __restrict__ bh2,
    const float* __restrict__ Wh3, const float* __restrict__ bh3,
    float* __restrict__ out, int max_pos)
{
    __shared__ float sbuf[1024];
    __shared__ int   mlist[MAXM];
    __shared__ int   mcount;
    const int tid = threadIdx.x;
    const int bid = blockIdx.x;
    unsigned mp0 = g_mph[0], mp1 = g_mph[1], mp2 = g_mph[2];

#define MARRIVE(id, total, mpv) do {                                         \
        __syncthreads();                                                     \
        if (tid == 0) {                                                      \
            __threadfence();                                                 \
            if (atomicAdd(&g_marr[id], 1) == (total) - 1) {                  \
                g_marr[id] = 0; __threadfence(); g_mph[id] = (mpv) + 1u;     \
            }                                                                \
        }                                                                    \
    } while (0)
#define MWAIT(id, mpv) do {                                                  \
        if (tid == 0) { while (g_mph[id] == (mpv)) { } __threadfence(); }    \
        __syncthreads();                                                     \
    } while (0)

    // ---- layer 1 (blocks 0..31): parallel match scan + reg accumulate ----
    {
        float* acc = sbuf;
        int ns1 = min(g_s1_count, MAX_S1);
        int nl1 = min(g_l1e_count, MAX_L1E);
        for (int s = bid; s < ns1; s += 32) {
            int node = g_s1_node[s];
            if (node < 0) continue;
            float degc = g_deg[node] + 1.0f;
            float dc = rsqrtf(degc);
            if (tid == 0) mcount = 0;
            __syncthreads();
            for (int e = tid; e < nl1; e += TTPB) {
                if (g_l1_cslot[e] == s) {
                    int p = atomicAdd(&mcount, 1);
                    if (p < MAXM) mlist[p] = e;
                }
            }
            __syncthreads();
            int mc = min(mcount, MAXM);
            float a = 0.0f;
            if (tid < 128) a = x[(size_t)node * 128 + tid] / degc;
            for (int m = 0; m < mc; m++) {
                int e = mlist[m];
                int r = g_l1_row[e];
                float norm = g_l1_w[e] * rsqrtf(g_deg[r] + 1.0f) * dc;
                if (tid < 128) a += norm * x[(size_t)r * 128 + tid];
            }
            if (tid < 128) acc[tid] = a;
            __syncthreads();
            if (tid < 256) {
                float aj = b1[tid];
#pragma unroll 8
                for (int k = 0; k < 128; k++) aj += acc[k] * W1[k * 256 + tid];
                g_h1[s * 256 + tid] = fmaxf(aj, 0.0f);
            }
            __syncthreads();
        }
    }
    MARRIVE(0, 32, mp0);
    if (bid >= 8) {
        // blocks 8..31: reset hash tables (unused by later tail phases)
        int base = (bid - 8) * TTPB + tid;
        int stride = 24 * TTPB;
        for (int i = base; i < H1TBL; i += stride) g_h1pack[i] = 0;
        for (int i = base; i < RTBL;  i += stride) g_rtab[i]  = 0;
        return;
    }

    // ---- layer 2 (blocks 0..7, 32 outputs each) ----
    MWAIT(0, mp0);
    {
        float* agg   = sbuf;           // 256
        float* spart = sbuf + 256;     // 256
        int ns2 = min(g_s2_count, MAX_S2);
        int nl2 = min(g_l2e_count, MAX_L2E);
        int j0 = bid * 32;
        float zacc = 0.0f;
        for (int s = 0; s < ns2; s++) {
            int cnode = g_s2_node[s];
            float degc = g_deg[cnode] + 1.0f;
            float dc = rsqrtf(degc);
            if (tid < 256) {
                int cs1 = g_s2_s1slot[s];
                float a = (cs1 >= 0) ? g_h1[cs1 * 256 + tid] / degc : 0.0f;
                for (int e = 0; e < nl2; e++) {
                    if (g_l2_cslot[e] == s) {
                        int rslot = g_l2_rslot[e];
                        if (rslot >= 0) {
                            int rnode = g_l2_row[e];
                            float norm = g_l2_w[e] * rsqrtf(g_deg[rnode] + 1.0f) * dc;
                            a += norm * g_h1[rslot * 256 + tid];
                        }
                    }
                }
                agg[tid] = a;
            }
            __syncthreads();
            if (tid < 256) {
                int kc = tid >> 5, j = tid & 31;
                float p = 0.0f;
#pragma unroll 8
                for (int k = kc * 32; k < kc * 32 + 32; k++)
                    p += agg[k] * W2[k * 256 + j0 + j];
                spart[tid] = p;
            }
            __syncthreads();
            if (tid < 32) {
                float sum = b2[j0 + tid];
#pragma unroll
                for (int c = 0; c < 8; c++) sum += spart[c * 32 + tid];
                zacc += g_s2_val[s] * fmaxf(sum, 0.0f);
            }
            __syncthreads();
        }
        if (tid < 32) g_z[j0 + tid] = zacc;
    }
    MARRIVE(1, 8, mp1);

    // ---- head GEMV1 480->512 (blocks 0..7, 64 outputs each) ----
    MWAIT(1, mp1);
    {
        float* feat  = sbuf;           // 480
        float* spart = sbuf + 480;     // 512
        int is32 = g_is32;
        int wtI  = is32 ? ((const int*)wt_idx)[0]  : (int)wt_idx[0];
        int mutI = is32 ? ((const int*)mut_idx)[0] : (int)mut_idx[0];
        if (tid < 256) feat[tid] = g_z[tid];
        else if (tid < 480) {
            int j = tid - 256;
            float v;
            if (j < 64)       v = aa_emb[wtI  * 64 + j];
            else if (j < 128) v = aa_emb[mutI * 64 + (j - 64)];
            else if (j < 192) v = aa_emb[mutI * 64 + (j - 128)] -
                                  aa_emb[wtI  * 64 + (j - 128)];
            else {
                unsigned int low = (unsigned int)(g_argmax_key & 0xFFFFFFFFull);
                int pos = (int)(0xFFFFFFFFu - low);
                if (pos < 0) pos = 0;
                if (pos > max_pos - 1) pos = max_pos - 1;
                v = pos_emb[pos * 32 + (j - 192)];
            }
            feat[tid] = v;
        }
        __syncthreads();
        int kc = tid >> 6, jj = tid & 63;
        int j  = bid * 64 + jj;
        float p = 0.0f;
#pragma unroll 10
        for (int k = kc * 60; k < kc * 60 + 60; k++)
            p += feat[k] * Wh1[k * 512 + j];
        spart[tid] = p;
        __syncthreads();
        if (tid < 64) {
            float sum = bh1[bid * 64 + tid];
#pragma unroll
            for (int c = 0; c < 8; c++) sum += spart[c * 64 + tid];
            g_f1[bid * 64 + tid] = fmaxf(sum, 0.0f);
        }
    }
    MARRIVE(2, 8, mp2);

    if (bid == 1) {
        MWAIT(2, mp2);
        if (tid == 0) {
            g_s2_count = 0; g_l2e_count = 0; g_l1e_count = 0;
            g_s1_count = 0; g_r_count = 0; g_is32 = 0;
            g_argmax_key = 0ull;
        }
        return;
    }
    if (bid != 0) return;

    // ---- head GEMV2 + final dot (block 0) ----
    MWAIT(2, mp2);
    {
        float* sf1   = sbuf;           // 512
        float* spart = sbuf + 512;     // 512
        sf1[tid] = g_f1[tid];
        __syncthreads();
        int kc = tid >> 7, j = tid & 127;
        float p = 0.0f;
#pragma unroll 8
        for (int k = kc * 128; k < kc * 128 + 128; k++)
            p += sf1[k] * Wh2[k * 128 + j];
        spart[kc * 128 + j] = p;
        __syncthreads();
        float* f2 = spart;
        if (tid < 128) {
            float sum = bh2[tid] + spart[tid] + spart[128 + tid] +
                        spart[256 + tid] + spart[384 + tid];
            f2[tid] = fmaxf(sum, 0.0f) * Wh3[tid];
        }
        __syncthreads();
        if (tid < 64) f2[tid] += f2[tid + 64];
        __syncthreads();
        if (tid < 32) {
            float v = f2[tid] + f2[tid + 32];
            for (int o = 16; o > 0; o >>= 1) v += __shfl_down_sync(0xFFFFFFFFu, v, o);
            if (tid == 0) out[0] = v + bh3[0];
        }
    }
#undef MARRIVE
#undef MWAIT
}

// ---------------------------------------------------------------------------
extern "C" void kernel_launch(void* const* d_in, const int* in_sizes, int n_in,
                              void* d_out, int out_size) {
    const float*     x       = (const float*)d_in[0];
    const long long* ei      = (const long long*)d_in[1];
    const float*     ew      = (const float*)d_in[2];
    const float*     mask    = (const float*)d_in[3];
    const long long* wt_idx  = (const long long*)d_in[4];
    const long long* mut_idx = (const long long*)d_in[5];
    const float*     W1      = (const float*)d_in[6];
    const float*     b1      = (const float*)d_in[7];
    const float*     W2      = (const float*)d_in[8];
    const float*     b2      = (const float*)d_in[9];
    const float*     aa_emb  = (const float*)d_in[10];
    const float*     pos_emb = (const float*)d_in[11];
    const float*     Wh1     = (const float*)d_in[12];
    const float*     bh1     = (const float*)d_in[13];
    const float*     Wh2     = (const float*)d_in[14];
    const float*     bh2     = (const float*)d_in[15];
    const float*     Wh3     = (const float*)d_in[16];
    const float*     bh3     = (const float*)d_in[17];
    float*           out     = (float*)d_out;

    int n       = in_sizes[3];
    int E       = in_sizes[2];
    int max_pos = in_sizes[11] / 32;

    k0_mask <<<(n + 255) / 256, 256>>>(mask, ei, n, E);
    k1_passA<<<GRIDP, 256>>>(ei, ew, E);
    k2_passB<<<GRIDP, 256>>>(ei, ew, E);
    k3_passC<<<GRIDP, 256>>>(ei, ew, E);
    k4_tail <<<32, TTPB>>>(x, wt_idx, mut_idx, W1, b1, W2, b2,
                           aa_emb, pos_emb, Wh1, bh1, Wh2, bh2, Wh3, bh3,
                           out, max_pos);
}